// round 6
// baseline (speedup 1.0000x reference)
#include <cuda_runtime.h>
#include <cstdint>
#include <cstddef>

// ---------------- problem constants (fixed by the dataset) ----------------
#define NN   16384      // nodes
#define NE   262144     // static edges (== NN * 16, also dynamic edge count)
#define DD   128        // node dim
#define DE   64         // edge dim
#define HH   256        // hidden
#define KK   16         // kNN

// ---------------- device scratch (allocation-free rule: __device__ globals) ----
__device__ float g_msg [(size_t)NE * 256];
__device__ float g_hid [(size_t)NE * 256];
__device__ float g_m   [(size_t)NE * 128];
__device__ float g_ea0 [(size_t)NE * DE];
__device__ float g_ea1 [(size_t)NE * DE];
__device__ float g_xs0 [NN * DD];
__device__ float g_xs1 [NN * DD];
__device__ float g_xd0 [NN * DD];
__device__ float g_xd1 [NN * DD];
__device__ float g_agg [NN * DD];
__device__ float g_tmpN[NN * HH];
__device__ float g_cat [NN * 2 * DD];
__device__ float g_sq  [NN];
__device__ float g_xT  [(size_t)DD * NN];
__device__ int   g_knn [NN * KK];
__device__ int   g_ei64flag;

// ---------------- edge_index dtype handling (int64 vs silently-int32) -----
__global__ void detect_ei_k(const void* p) {
    const unsigned long long* q = (const unsigned long long*)p;
    int ok = 1;
    #pragma unroll
    for (int i = 0; i < 8; i++)
        if (q[i] >= (unsigned long long)NN) ok = 0;
    g_ei64flag = ok;
}

__device__ __forceinline__ long long load_ei(const void* p, long long idx) {
    if (g_ei64flag) return ((const long long*)p)[idx];
    return (long long)((const int*)p)[idx];
}

// ---------------- tf32 helpers ----------------------------------------------
__device__ __forceinline__ float f2tf(float x) {
    uint32_t u;
    asm("cvt.rna.tf32.f32 %0, %1;" : "=r"(u) : "f"(x));
    return __uint_as_float(u);
}

#define MMA_TF32(acc, a0, a1, a2, a3, b0, b1)                                  \
    asm volatile(                                                              \
        "mma.sync.aligned.m16n8k8.row.col.f32.tf32.tf32.f32 "                  \
        "{%0,%1,%2,%3}, {%4,%5,%6,%7}, {%8,%9}, {%0,%1,%2,%3};"                \
        : "+f"(acc[0]), "+f"(acc[1]), "+f"(acc[2]), "+f"(acc[3])               \
        : "r"(a0), "r"(a1), "r"(a2), "r"(a3), "r"(b0), "r"(b1))

// ---------------- 3xTF32 tensor-core GEMM (fp32-accurate) --------------------
// Raw fp32 tiles in smem; hi/lo computed at fragment-read time.
// C = epi(A[MxK] @ B[KxN] + bias).  Requires M%128==0, N%128==0, K%32==0.
// mode 0: relu(acc + bias[col])
#define TBM 128
#define TBN 128
#define TBK 32
#define ASTR 36
#define BSTR 136

__global__ __launch_bounds__(256, 2) void mma3_gemm_k(
    const float* __restrict__ A, const float* __restrict__ B,
    const float* __restrict__ bias, float* __restrict__ C,
    int M, int K, int N, int mode)
{
    __shared__ float As[TBM * ASTR];   // raw fp32, 18KB
    __shared__ float Bs[TBK * BSTR];   // raw fp32, 17KB

    const int tid  = threadIdx.x;
    const int lane = tid & 31;
    const int warp = tid >> 5;
    const int warp_m = warp & 1;
    const int warp_n = warp >> 1;
    const int row0 = blockIdx.y * TBM;
    const int col0 = blockIdx.x * TBN;
    const int g  = lane >> 2;
    const int tg = lane & 3;

    float acc[4][4][4];
    #pragma unroll
    for (int mm = 0; mm < 4; mm++)
        #pragma unroll
        for (int nn = 0; nn < 4; nn++)
            #pragma unroll
            for (int r = 0; r < 4; r++) acc[mm][nn][r] = 0.f;

    const int ktiles = K / TBK;
    for (int kt = 0; kt < ktiles; kt++) {
        #pragma unroll
        for (int p = 0; p < 4; p++) {
            const int lin = tid + 256 * p;
            const int r  = lin >> 3;
            const int c4 = lin & 7;
            *(float4*)&As[r * ASTR + c4 * 4] =
                *(const float4*)(A + (size_t)(row0 + r) * K + kt * TBK + c4 * 4);
        }
        #pragma unroll
        for (int p = 0; p < 4; p++) {
            const int lin = tid + 256 * p;
            const int kr = lin >> 5;
            const int c4 = lin & 31;
            *(float4*)&Bs[kr * BSTR + c4 * 4] =
                *(const float4*)(B + (size_t)(kt * TBK + kr) * N + col0 + c4 * 4);
        }
        __syncthreads();

        #pragma unroll
        for (int kk = 0; kk < 4; kk++) {
            const int kb = kk * 8;
            uint32_t af[4][4], bf[4][2];
            float braw[4][2];

            // A-hi fragments (raw read + cvt)
            #pragma unroll
            for (int mm = 0; mm < 4; mm++) {
                const int ar = warp_m * 64 + mm * 16 + g;
                af[mm][0] = __float_as_uint(f2tf(As[ar * ASTR + kb + tg]));
                af[mm][1] = __float_as_uint(f2tf(As[(ar + 8) * ASTR + kb + tg]));
                af[mm][2] = __float_as_uint(f2tf(As[ar * ASTR + kb + tg + 4]));
                af[mm][3] = __float_as_uint(f2tf(As[(ar + 8) * ASTR + kb + tg + 4]));
            }
            // B raw (kept in regs across all passes); pass 1 uses B-lo
            #pragma unroll
            for (int nn = 0; nn < 4; nn++) {
                const int bc = warp_n * 32 + nn * 8 + g;
                braw[nn][0] = Bs[(kb + tg) * BSTR + bc];
                braw[nn][1] = Bs[(kb + tg + 4) * BSTR + bc];
                bf[nn][0] = __float_as_uint(f2tf(braw[nn][0] - f2tf(braw[nn][0])));
                bf[nn][1] = __float_as_uint(f2tf(braw[nn][1] - f2tf(braw[nn][1])));
            }
            #pragma unroll
            for (int mm = 0; mm < 4; mm++)
                #pragma unroll
                for (int nn = 0; nn < 4; nn++)
                    MMA_TF32(acc[mm][nn], af[mm][0], af[mm][1], af[mm][2], af[mm][3],
                             bf[nn][0], bf[nn][1]);
            // pass 2: A-hi x B-hi
            #pragma unroll
            for (int nn = 0; nn < 4; nn++) {
                bf[nn][0] = __float_as_uint(f2tf(braw[nn][0]));
                bf[nn][1] = __float_as_uint(f2tf(braw[nn][1]));
            }
            #pragma unroll
            for (int mm = 0; mm < 4; mm++)
                #pragma unroll
                for (int nn = 0; nn < 4; nn++)
                    MMA_TF32(acc[mm][nn], af[mm][0], af[mm][1], af[mm][2], af[mm][3],
                             bf[nn][0], bf[nn][1]);
            // pass 3: A-lo x B-hi (re-read raw A)
            #pragma unroll
            for (int mm = 0; mm < 4; mm++) {
                const int ar = warp_m * 64 + mm * 16 + g;
                float r0 = As[ar * ASTR + kb + tg];
                float r1 = As[(ar + 8) * ASTR + kb + tg];
                float r2 = As[ar * ASTR + kb + tg + 4];
                float r3 = As[(ar + 8) * ASTR + kb + tg + 4];
                af[mm][0] = __float_as_uint(f2tf(r0 - f2tf(r0)));
                af[mm][1] = __float_as_uint(f2tf(r1 - f2tf(r1)));
                af[mm][2] = __float_as_uint(f2tf(r2 - f2tf(r2)));
                af[mm][3] = __float_as_uint(f2tf(r3 - f2tf(r3)));
            }
            #pragma unroll
            for (int mm = 0; mm < 4; mm++)
                #pragma unroll
                for (int nn = 0; nn < 4; nn++)
                    MMA_TF32(acc[mm][nn], af[mm][0], af[mm][1], af[mm][2], af[mm][3],
                             bf[nn][0], bf[nn][1]);
        }
        __syncthreads();
    }

    #pragma unroll
    for (int nn = 0; nn < 4; nn++) {
        const int col = col0 + warp_n * 32 + nn * 8 + tg * 2;
        const float bv0 = bias[col], bv1 = bias[col + 1];
        #pragma unroll
        for (int mm = 0; mm < 4; mm++) {
            const int row = row0 + warp_m * 64 + mm * 16 + g;
            float2 o0, o1;
            o0.x = fmaxf(acc[mm][nn][0] + bv0, 0.f);
            o0.y = fmaxf(acc[mm][nn][1] + bv1, 0.f);
            o1.x = fmaxf(acc[mm][nn][2] + bv0, 0.f);
            o1.y = fmaxf(acc[mm][nn][3] + bv1, 0.f);
            *(float2*)(C + (size_t)row * N + col)       = o0;
            *(float2*)(C + (size_t)(row + 8) * N + col) = o1;
        }
    }
}

// ---------------- fused distance GEMM + per-row top-16 ----------------------
// Block = 64 rows; sweeps all 128 column tiles of dist = sq[j] - 2 * xd @ xT.
// A (64x128) cached in smem for the whole block; per-thread register top-16
// over disjoint column sets; final 4-way merge per row.
#define DTM 64
#define FASTR 132               // A: [64][132] raw fp32
#define SPITCH 132              // scores: [64][132]
#define DT_A_SZ   (DTM * FASTR)            // 8448 floats
#define DT_B_SZ   (TBK * BSTR)             // 4352 floats
#define DT_S_SZ   (DTM * SPITCH)           // 8448 floats
#define DT_SMEM_BYTES ((DT_A_SZ + DT_B_SZ + DT_S_SZ) * 4)   // 85 KB? -> 84992 B

__global__ __launch_bounds__(256, 2) void dist_topk_k(
    const float* __restrict__ X, const float* __restrict__ XT,
    const float* __restrict__ sq, int* __restrict__ knn)
{
    extern __shared__ float sm[];
    float* As = sm;                       // [64][FASTR]
    float* Bs = sm + DT_A_SZ;             // [32][BSTR]
    float* Sc = sm + DT_A_SZ + DT_B_SZ;   // [64][SPITCH]

    const int tid  = threadIdx.x;
    const int lane = tid & 31;
    const int warp = tid >> 5;
    const int warp_m = warp & 1;     // 32 rows each
    const int warp_n = warp >> 1;    // 32 cols each
    const int row0 = blockIdx.x * DTM;
    const int g  = lane >> 2;
    const int tg = lane & 3;

    // load A (64 x 128) once
    #pragma unroll
    for (int p = 0; p < 8; p++) {
        const int lin = tid + 256 * p;
        const int r  = lin >> 5;
        const int c4 = lin & 31;
        *(float4*)&As[r * FASTR + c4 * 4] =
            *(const float4*)(X + (size_t)(row0 + r) * DD + c4 * 4);
    }

    // per-thread top-16 (ascending (val, idx))
    float ld[KK]; int li[KK];
    #pragma unroll
    for (int q = 0; q < KK; q++) { ld[q] = __int_as_float(0x7f800000); li[q] = 0x7FFFFFFF; }
    float worst = __int_as_float(0x7f800000); int worsti = 0x7FFFFFFF;
    const int srow = tid >> 2;       // scan row (0..63)
    const int sp   = tid & 3;        // scan sub-lane (0..3)

    __syncthreads();

    for (int tile = 0; tile < NN / TBN; tile++) {
        const int col0 = tile * TBN;

        float acc[2][4][4];
        #pragma unroll
        for (int mm = 0; mm < 2; mm++)
            #pragma unroll
            for (int nn = 0; nn < 4; nn++)
                #pragma unroll
                for (int r = 0; r < 4; r++) acc[mm][nn][r] = 0.f;

        #pragma unroll
        for (int kt = 0; kt < 4; kt++) {
            #pragma unroll
            for (int p = 0; p < 4; p++) {
                const int lin = tid + 256 * p;
                const int kr = lin >> 5;
                const int c4 = lin & 31;
                *(float4*)&Bs[kr * BSTR + c4 * 4] =
                    *(const float4*)(XT + (size_t)(kt * TBK + kr) * NN + col0 + c4 * 4);
            }
            __syncthreads();

            #pragma unroll
            for (int kk = 0; kk < 4; kk++) {
                const int kb = kt * TBK + kk * 8;   // k offset into As
                const int kbb = kk * 8;             // k offset into Bs
                uint32_t af[2][4], bf[4][2];
                float braw[4][2];

                #pragma unroll
                for (int mm = 0; mm < 2; mm++) {
                    const int ar = warp_m * 32 + mm * 16 + g;
                    af[mm][0] = __float_as_uint(f2tf(As[ar * FASTR + kb + tg]));
                    af[mm][1] = __float_as_uint(f2tf(As[(ar + 8) * FASTR + kb + tg]));
                    af[mm][2] = __float_as_uint(f2tf(As[ar * FASTR + kb + tg + 4]));
                    af[mm][3] = __float_as_uint(f2tf(As[(ar + 8) * FASTR + kb + tg + 4]));
                }
                #pragma unroll
                for (int nn = 0; nn < 4; nn++) {
                    const int bc = warp_n * 32 + nn * 8 + g;
                    braw[nn][0] = Bs[(kbb + tg) * BSTR + bc];
                    braw[nn][1] = Bs[(kbb + tg + 4) * BSTR + bc];
                    bf[nn][0] = __float_as_uint(f2tf(braw[nn][0] - f2tf(braw[nn][0])));
                    bf[nn][1] = __float_as_uint(f2tf(braw[nn][1] - f2tf(braw[nn][1])));
                }
                #pragma unroll
                for (int mm = 0; mm < 2; mm++)
                    #pragma unroll
                    for (int nn = 0; nn < 4; nn++)
                        MMA_TF32(acc[mm][nn], af[mm][0], af[mm][1], af[mm][2], af[mm][3],
                                 bf[nn][0], bf[nn][1]);
                #pragma unroll
                for (int nn = 0; nn < 4; nn++) {
                    bf[nn][0] = __float_as_uint(f2tf(braw[nn][0]));
                    bf[nn][1] = __float_as_uint(f2tf(braw[nn][1]));
                }
                #pragma unroll
                for (int mm = 0; mm < 2; mm++)
                    #pragma unroll
                    for (int nn = 0; nn < 4; nn++)
                        MMA_TF32(acc[mm][nn], af[mm][0], af[mm][1], af[mm][2], af[mm][3],
                                 bf[nn][0], bf[nn][1]);
                #pragma unroll
                for (int mm = 0; mm < 2; mm++) {
                    const int ar = warp_m * 32 + mm * 16 + g;
                    float r0 = As[ar * FASTR + kb + tg];
                    float r1 = As[(ar + 8) * FASTR + kb + tg];
                    float r2 = As[ar * FASTR + kb + tg + 4];
                    float r3 = As[(ar + 8) * FASTR + kb + tg + 4];
                    af[mm][0] = __float_as_uint(f2tf(r0 - f2tf(r0)));
                    af[mm][1] = __float_as_uint(f2tf(r1 - f2tf(r1)));
                    af[mm][2] = __float_as_uint(f2tf(r2 - f2tf(r2)));
                    af[mm][3] = __float_as_uint(f2tf(r3 - f2tf(r3)));
                }
                #pragma unroll
                for (int mm = 0; mm < 2; mm++)
                    #pragma unroll
                    for (int nn = 0; nn < 4; nn++)
                        MMA_TF32(acc[mm][nn], af[mm][0], af[mm][1], af[mm][2], af[mm][3],
                                 bf[nn][0], bf[nn][1]);
            }
            __syncthreads();
        }

        // epilogue: dist = sq[col] - 2*acc -> scores smem
        #pragma unroll
        for (int nn = 0; nn < 4; nn++) {
            const int coll = warp_n * 32 + nn * 8 + tg * 2;
            const float s0 = sq[col0 + coll], s1 = sq[col0 + coll + 1];
            #pragma unroll
            for (int mm = 0; mm < 2; mm++) {
                const int rl = warp_m * 32 + mm * 16 + g;
                float2 o0, o1;
                o0.x = s0 - 2.f * acc[mm][nn][0];
                o0.y = s1 - 2.f * acc[mm][nn][1];
                o1.x = s0 - 2.f * acc[mm][nn][2];
                o1.y = s1 - 2.f * acc[mm][nn][3];
                *(float2*)&Sc[rl * SPITCH + coll]       = o0;
                *(float2*)&Sc[(rl + 8) * SPITCH + coll] = o1;
            }
        }
        __syncthreads();

        // scan: 4 threads per row, 32 columns each (j = 4c + sp)
        #pragma unroll 4
        for (int c = 0; c < 32; c++) {
            const int j = 4 * c + sp;
            const float v = Sc[srow * SPITCH + j];
            const int gj = col0 + j;
            if (v < worst || (v == worst && gj < worsti)) {
                int p = KK - 1;
                while (p > 0) {
                    const bool gt = (ld[p-1] > v) || (ld[p-1] == v && li[p-1] > gj);
                    if (!gt) break;
                    ld[p] = ld[p-1]; li[p] = li[p-1]; p--;
                }
                ld[p] = v; li[p] = gj;
                worst = ld[KK-1]; worsti = li[KK-1];
            }
        }
        __syncthreads();
    }

    // merge 4 per-thread lists per row (reuse scores smem)
    float* mv = Sc;                       // 64*4*16 = 4096 floats
    int*   mi = (int*)(Sc + 4096);
    #pragma unroll
    for (int q = 0; q < KK; q++) {
        mv[(srow * 4 + sp) * KK + q] = ld[q];
        mi[(srow * 4 + sp) * KK + q] = li[q];
    }
    __syncthreads();

    if (tid < DTM) {
        const int r = tid;
        int ptr[4] = {0, 0, 0, 0};
        #pragma unroll
        for (int q = 0; q < KK; q++) {
            float bv = __int_as_float(0x7f800000); int bi = 0x7FFFFFFF; int bs = 0;
            #pragma unroll
            for (int s = 0; s < 4; s++) {
                const float v = mv[(r * 4 + s) * KK + ptr[s]];
                const int   i = mi[(r * 4 + s) * KK + ptr[s]];
                if (v < bv || (v == bv && i < bi)) { bv = v; bi = i; bs = s; }
            }
            ptr[bs]++;
            knn[(row0 + r) * KK + q] = bi;
        }
    }
}

// ---------------- fallback SIMT GEMM (used only when N % 128 != 0) ----------
#define GBM 128
#define GBN 64
#define GBK 32

__global__ __launch_bounds__(256, 2) void gemm_k(
    const float* __restrict__ A, const float* __restrict__ B,
    const float* __restrict__ bias, float* __restrict__ C,
    int M, int K, int N, int mode)
{
    __shared__ float As[GBK][GBM + 4];
    __shared__ float Bs[GBK][GBN];
    const int tid  = threadIdx.x;
    const int row0 = blockIdx.y * GBM;
    const int col0 = blockIdx.x * GBN;
    const int tr = tid >> 4;
    const int tc = tid & 15;

    float acc[8][4];
    #pragma unroll
    for (int i = 0; i < 8; i++)
        #pragma unroll
        for (int j = 0; j < 4; j++) acc[i][j] = 0.f;

    const int ktiles = K / GBK;
    for (int kt = 0; kt < ktiles; kt++) {
        #pragma unroll
        for (int p = 0; p < 4; p++) {
            int lin = tid + 256 * p;
            int r = lin >> 3, q = lin & 7;
            const float4 v = *(const float4*)(A + (size_t)(row0 + r) * K + kt * GBK + q * 4);
            As[q * 4 + 0][r] = v.x; As[q * 4 + 1][r] = v.y;
            As[q * 4 + 2][r] = v.z; As[q * 4 + 3][r] = v.w;
        }
        #pragma unroll
        for (int p = 0; p < 2; p++) {
            int lin = tid + 256 * p;
            int kr = lin >> 4, j4 = lin & 15;
            *(float4*)&Bs[kr][j4 * 4] =
                *(const float4*)(B + (size_t)(kt * GBK + kr) * N + col0 + j4 * 4);
        }
        __syncthreads();
        #pragma unroll
        for (int k = 0; k < GBK; k++) {
            float a[8], b[4];
            *(float4*)&a[0] = *(const float4*)&As[k][tr * 8];
            *(float4*)&a[4] = *(const float4*)&As[k][tr * 8 + 4];
            *(float4*)&b[0] = *(const float4*)&Bs[k][tc * 4];
            #pragma unroll
            for (int i = 0; i < 8; i++)
                #pragma unroll
                for (int j = 0; j < 4; j++)
                    acc[i][j] = fmaf(a[i], b[j], acc[i][j]);
        }
        __syncthreads();
    }

    float bv[4];
    #pragma unroll
    for (int j = 0; j < 4; j++) bv[j] = bias[col0 + tc * 4 + j];

    #pragma unroll
    for (int i = 0; i < 8; i++) {
        const int row = row0 + tr * 8 + i;
        float4 o;
        o.x = fmaxf(acc[i][0] + bv[0], 0.f);
        o.y = fmaxf(acc[i][1] + bv[1], 0.f);
        o.z = fmaxf(acc[i][2] + bv[2], 0.f);
        o.w = fmaxf(acc[i][3] + bv[3], 0.f);
        *(float4*)(C + (size_t)row * N + col0 + tc * 4) = o;
    }
}

// ---------------- small helper kernels --------------------------------------
__global__ void build_smsg_k(const float* __restrict__ ea, const float* __restrict__ xs,
                             const void* __restrict__ ei, float* __restrict__ msg)
{
    const int e = blockIdx.x, t = threadIdx.x;
    if (t < DE) {
        msg[(size_t)e * 192 + t] = ea[(size_t)e * DE + t];
    } else {
        const long long s = load_ei(ei, e);
        const long long d = load_ei(ei, (long long)NE + e);
        const int c = t - DE;
        msg[(size_t)e * 192 + t] = xs[s * DD + c] - xs[d * DD + c];
    }
}

__global__ void scatter_add_k(float* __restrict__ agg, const float* __restrict__ m,
                              const void* __restrict__ ei)
{
    const int e = blockIdx.x, t = threadIdx.x;
    const long long d = load_ei(ei, (long long)NE + e);
    atomicAdd(&agg[d * DD + t], m[(size_t)e * DD + t]);
}

__global__ void rownorm_k(const float* __restrict__ x, float* __restrict__ sq)
{
    const int row  = blockIdx.x * 8 + (threadIdx.x >> 5);
    const int lane = threadIdx.x & 31;
    const float* p = x + (size_t)row * DD;
    float s = 0.f;
    #pragma unroll
    for (int q = 0; q < 4; q++) { float v = p[lane + 32 * q]; s = fmaf(v, v, s); }
    #pragma unroll
    for (int o = 16; o > 0; o >>= 1) s += __shfl_xor_sync(0xffffffffu, s, o);
    if (lane == 0) sq[row] = s;
}

__global__ void transpose_k(const float* __restrict__ in, float* __restrict__ out)
{
    __shared__ float t[32][33];
    const int j0 = blockIdx.x * 32, k0 = blockIdx.y * 32;
    for (int r = threadIdx.y; r < 32; r += 8)
        t[r][threadIdx.x] = in[(size_t)(j0 + r) * DD + k0 + threadIdx.x];
    __syncthreads();
    for (int r = threadIdx.y; r < 32; r += 8)
        out[(size_t)(k0 + r) * NN + j0 + threadIdx.x] = t[threadIdx.x][r];
}

__global__ void build_dmsg_k(const float* __restrict__ xd, const int* __restrict__ knn,
                             float* __restrict__ msg)
{
    const int e = blockIdx.x, c = threadIdx.x;
    const int i = e >> 4;
    const int j = knn[e];
    const int cc = c & 127;
    const float xi = xd[i * DD + cc];
    const float v  = (c < DD) ? xi : (xd[j * DD + cc] - xi);
    msg[(size_t)e * 256 + c] = v;
}

__global__ void dyn_agg_k(const float* __restrict__ m, float* __restrict__ agg)
{
    const int i = blockIdx.x, d = threadIdx.x;
    const float* p = m + (size_t)i * KK * DD + d;
    float s = 0.f;
    #pragma unroll
    for (int t = 0; t < KK; t++) s += p[t * DD];
    agg[i * DD + d] = s;
}

__global__ void concat_k(const float* __restrict__ a, const float* __restrict__ b,
                         float* __restrict__ out)
{
    const int i = blockIdx.x, c = threadIdx.x;
    out[(size_t)i * 256 + c] = (c < DD) ? a[i * DD + c] : b[i * DD + c - DD];
}

// ---------------- host orchestration ---------------------------------------
static inline void gemm(const float* A, const float* B, const float* bias, float* C,
                        int M, int K, int N, int mode)
{
    if ((N % TBN) == 0 && (M % TBM) == 0) {
        dim3 g(N / TBN, M / TBM);
        mma3_gemm_k<<<g, 256>>>(A, B, bias, C, M, K, N, mode);
    } else {
        dim3 g(N / GBN, M / GBM);
        gemm_k<<<g, 256>>>(A, B, bias, C, M, K, N, mode);
    }
}

extern "C" void kernel_launch(void* const* d_in, const int* in_sizes, int n_in,
                              void* d_out, int out_size)
{
    const float* x    = (const float*)d_in[0];
    const float* ea_i = (const float*)d_in[1];
    const float* sW1  = (const float*)d_in[2];
    const float* sb1  = (const float*)d_in[3];
    const float* sW2  = (const float*)d_in[4];
    const float* sb2  = (const float*)d_in[5];
    const float* uW1  = (const float*)d_in[6];
    const float* ub1  = (const float*)d_in[7];
    const float* uW2  = (const float*)d_in[8];
    const float* ub2  = (const float*)d_in[9];
    const float* rW   = (const float*)d_in[10];
    const float* rb   = (const float*)d_in[11];
    const float* dW1  = (const float*)d_in[12];
    const float* db1  = (const float*)d_in[13];
    const float* dW2  = (const float*)d_in[14];
    const float* db2  = (const float*)d_in[15];
    const float* dUW1 = (const float*)d_in[16];
    const float* dUb1 = (const float*)d_in[17];
    const float* dUW2 = (const float*)d_in[18];
    const float* dUb2 = (const float*)d_in[19];
    const float* fW1  = (const float*)d_in[20];
    const float* fb1  = (const float*)d_in[21];
    const float* fW2  = (const float*)d_in[22];
    const float* fb2  = (const float*)d_in[23];
    const void*  ei   = d_in[24];

    cudaFuncSetAttribute(dist_topk_k, cudaFuncAttributeMaxDynamicSharedMemorySize,
                         DT_SMEM_BYTES);

    float *msg, *hid, *m, *ea0, *ea1, *xs0, *xs1, *xd0, *xd1;
    float *agg, *tmpN, *cat, *sq, *xT;
    int   *knn;
    cudaGetSymbolAddress((void**)&msg,  g_msg);
    cudaGetSymbolAddress((void**)&hid,  g_hid);
    cudaGetSymbolAddress((void**)&m,    g_m);
    cudaGetSymbolAddress((void**)&ea0,  g_ea0);
    cudaGetSymbolAddress((void**)&ea1,  g_ea1);
    cudaGetSymbolAddress((void**)&xs0,  g_xs0);
    cudaGetSymbolAddress((void**)&xs1,  g_xs1);
    cudaGetSymbolAddress((void**)&xd0,  g_xd0);
    cudaGetSymbolAddress((void**)&xd1,  g_xd1);
    cudaGetSymbolAddress((void**)&agg,  g_agg);
    cudaGetSymbolAddress((void**)&tmpN, g_tmpN);
    cudaGetSymbolAddress((void**)&cat,  g_cat);
    cudaGetSymbolAddress((void**)&sq,   g_sq);
    cudaGetSymbolAddress((void**)&xT,   g_xT);
    cudaGetSymbolAddress((void**)&knn,  g_knn);

    detect_ei_k<<<1, 1>>>(ei);

    // ---------------- static branch: 3 conv layers + 2 edge refiners --------
    const float* xs_in = x;
    const float* ea_in = ea_i;
    float* xs_bufs[2] = { xs0, xs1 };
    float* ea_bufs[2] = { ea0, ea1 };
    for (int i = 0; i < 3; i++) {
        build_smsg_k<<<NE, 192>>>(ea_in, xs_in, ei, msg);
        gemm(msg, sW1 + (size_t)i * 192 * HH, sb1 + i * HH, hid, NE, 192, HH, 0);
        gemm(hid, sW2 + (size_t)i * HH * DD,  sb2 + i * DD, m,   NE, HH, DD, 0);
        cudaMemsetAsync(agg, 0, (size_t)NN * DD * sizeof(float));
        scatter_add_k<<<NE, DD>>>(agg, m, ei);
        gemm(agg,  uW1 + (size_t)i * DD * HH, ub1 + i * HH, tmpN, NN, DD, HH, 0);
        float* xs_out = xs_bufs[i & 1];
        gemm(tmpN, uW2 + (size_t)i * HH * DD, ub2 + i * DD, xs_out, NN, HH, DD, 0);
        if (i < 2) {
            float* ea_out = ea_bufs[i & 1];
            gemm(ea_in, rW + (size_t)i * DE * DE, rb + i * DE, ea_out, NE, DE, DE, 0);
            ea_in = ea_out;
        }
        xs_in = xs_out;
    }

    // ---------------- dynamic branch: 2 kNN conv layers ---------------------
    const float* xd_in = x;
    float* xd_bufs[2] = { xd0, xd1 };
    for (int i = 0; i < 2; i++) {
        rownorm_k<<<NN / 8, 256>>>(xd_in, sq);
        transpose_k<<<dim3(NN / 32, DD / 32), dim3(32, 8)>>>(xd_in, xT);
        dist_topk_k<<<NN / DTM, 256, DT_SMEM_BYTES>>>(xd_in, xT, sq, knn);
        build_dmsg_k<<<NE, 256>>>(xd_in, knn, msg);
        gemm(msg, dW1 + (size_t)i * 256 * HH, db1 + i * HH, hid, NE, 256, HH, 0);
        gemm(hid, dW2 + (size_t)i * HH * DD,  db2 + i * DD, m,   NE, HH, DD, 0);
        dyn_agg_k<<<NN, DD>>>(m, agg);
        gemm(agg,  dUW1 + (size_t)i * DD * HH, dUb1 + i * HH, tmpN, NN, DD, HH, 0);
        float* xd_out = xd_bufs[i];
        gemm(tmpN, dUW2 + (size_t)i * HH * DD, dUb2 + i * DD, xd_out, NN, HH, DD, 0);
        xd_in = xd_out;
    }

    // ---------------- fuse ---------------------------------------------------
    concat_k<<<NN, 256>>>(xs_in, xd_in, cat);
    gemm(cat,  fW1, fb1, tmpN, NN, 2 * DD, HH, 0);
    gemm(tmpN, fW2, fb2, (float*)d_out, NN, HH, DD, 0);
}

// round 7
// speedup vs baseline: 1.4403x; 1.4403x over previous
#include <cuda_runtime.h>
#include <cstdint>
#include <cstddef>

// ---------------- problem constants (fixed by the dataset) ----------------
#define NN   16384      // nodes
#define NE   262144     // static edges (== NN * 16, also dynamic edge count)
#define DD   128        // node dim
#define DE   64         // edge dim
#define HH   256        // hidden
#define KK   16         // kNN

// ---------------- device scratch (allocation-free rule: __device__ globals) ----
__device__ float g_msg [(size_t)NE * 256];
__device__ float g_hid [(size_t)NE * 256];
__device__ float g_m   [(size_t)NE * 128];
__device__ float g_ea0 [(size_t)NE * DE];
__device__ float g_ea1 [(size_t)NE * DE];
__device__ float g_xs0 [NN * DD];
__device__ float g_xs1 [NN * DD];
__device__ float g_xd0 [NN * DD];
__device__ float g_xd1 [NN * DD];
__device__ float g_agg [NN * DD];
__device__ float g_tmpN[NN * HH];
__device__ float g_P2  [NN * HH];
__device__ float g_cat [NN * 2 * DD];
__device__ float g_sq  [NN];
__device__ float g_xT  [(size_t)DD * NN];
__device__ float g_dist[(size_t)NN * NN];
__device__ int   g_knn [NN * KK];
__device__ float g_zero[HH];          // zero-initialized bias
__device__ int   g_ei64flag;

// ---------------- edge_index dtype handling (int64 vs silently-int32) -----
__global__ void detect_ei_k(const void* p) {
    const unsigned long long* q = (const unsigned long long*)p;
    int ok = 1;
    #pragma unroll
    for (int i = 0; i < 8; i++)
        if (q[i] >= (unsigned long long)NN) ok = 0;
    g_ei64flag = ok;
}

__device__ __forceinline__ long long load_ei(const void* p, long long idx) {
    if (g_ei64flag) return ((const long long*)p)[idx];
    return (long long)((const int*)p)[idx];
}

// ---------------- tf32 helpers ----------------------------------------------
__device__ __forceinline__ float f2tf(float x) {
    uint32_t u;
    asm("cvt.rna.tf32.f32 %0, %1;" : "=r"(u) : "f"(x));
    return __uint_as_float(u);
}

#define MMA_TF32(acc, a0, a1, a2, a3, b0, b1)                                  \
    asm volatile(                                                              \
        "mma.sync.aligned.m16n8k8.row.col.f32.tf32.tf32.f32 "                  \
        "{%0,%1,%2,%3}, {%4,%5,%6,%7}, {%8,%9}, {%0,%1,%2,%3};"                \
        : "+f"(acc[0]), "+f"(acc[1]), "+f"(acc[2]), "+f"(acc[3])               \
        : "r"(a0), "r"(a1), "r"(a2), "r"(a3), "r"(b0), "r"(b1))

// ---------------- 3xTF32 tensor-core GEMM (fp32-accurate, R5 layout) ---------
// C = epi(A[MxK] @ B[KxN] + bias).  Requires M%128==0, N%128==0, K%32==0.
// mode 0: relu(acc+bias);  mode 1: bias - 2*acc (knn);  mode 2: acc+bias
#define TBM 128
#define TBN 128
#define TBK 32
#define ASTR 36
#define BSTR 136
#define A_SZ (TBM * ASTR)
#define B_SZ (TBK * BSTR)
#define MMA3_SMEM_BYTES ((2 * A_SZ + 2 * B_SZ) * 4)   // 71680 B

__global__ __launch_bounds__(256, 2) void mma3_gemm_k(
    const float* __restrict__ A, const float* __restrict__ B,
    const float* __restrict__ bias, float* __restrict__ C,
    int M, int K, int N, int mode)
{
    extern __shared__ float sm[];
    float* Ah = sm;
    float* Al = sm + A_SZ;
    float* Bh = sm + 2 * A_SZ;
    float* Bl = sm + 2 * A_SZ + B_SZ;

    const int tid  = threadIdx.x;
    const int lane = tid & 31;
    const int warp = tid >> 5;
    const int warp_m = warp & 1;
    const int warp_n = warp >> 1;
    const int row0 = blockIdx.y * TBM;
    const int col0 = blockIdx.x * TBN;
    const int g  = lane >> 2;
    const int tg = lane & 3;

    float acc[4][4][4];
    #pragma unroll
    for (int mm = 0; mm < 4; mm++)
        #pragma unroll
        for (int nn = 0; nn < 4; nn++)
            #pragma unroll
            for (int r = 0; r < 4; r++) acc[mm][nn][r] = 0.f;

    const int ktiles = K / TBK;
    for (int kt = 0; kt < ktiles; kt++) {
        #pragma unroll
        for (int p = 0; p < 4; p++) {
            const int lin = tid + 256 * p;
            const int r  = lin >> 3;
            const int c4 = lin & 7;
            const float4 v = *(const float4*)(A + (size_t)(row0 + r) * K + kt * TBK + c4 * 4);
            float4 vh, vl;
            vh.x = f2tf(v.x); vl.x = f2tf(v.x - vh.x);
            vh.y = f2tf(v.y); vl.y = f2tf(v.y - vh.y);
            vh.z = f2tf(v.z); vl.z = f2tf(v.z - vh.z);
            vh.w = f2tf(v.w); vl.w = f2tf(v.w - vh.w);
            *(float4*)&Ah[r * ASTR + c4 * 4] = vh;
            *(float4*)&Al[r * ASTR + c4 * 4] = vl;
        }
        #pragma unroll
        for (int p = 0; p < 4; p++) {
            const int lin = tid + 256 * p;
            const int kr = lin >> 5;
            const int c4 = lin & 31;
            const float4 v = *(const float4*)(B + (size_t)(kt * TBK + kr) * N + col0 + c4 * 4);
            float4 vh, vl;
            vh.x = f2tf(v.x); vl.x = f2tf(v.x - vh.x);
            vh.y = f2tf(v.y); vl.y = f2tf(v.y - vh.y);
            vh.z = f2tf(v.z); vl.z = f2tf(v.z - vh.z);
            vh.w = f2tf(v.w); vl.w = f2tf(v.w - vh.w);
            *(float4*)&Bh[kr * BSTR + c4 * 4] = vh;
            *(float4*)&Bl[kr * BSTR + c4 * 4] = vl;
        }
        __syncthreads();

        #pragma unroll
        for (int kk = 0; kk < 4; kk++) {
            const int kb = kk * 8;
            uint32_t af[4][4], bf[4][2];

            #pragma unroll
            for (int mm = 0; mm < 4; mm++) {
                const int ar = warp_m * 64 + mm * 16 + g;
                af[mm][0] = __float_as_uint(Ah[ar * ASTR + kb + tg]);
                af[mm][1] = __float_as_uint(Ah[(ar + 8) * ASTR + kb + tg]);
                af[mm][2] = __float_as_uint(Ah[ar * ASTR + kb + tg + 4]);
                af[mm][3] = __float_as_uint(Ah[(ar + 8) * ASTR + kb + tg + 4]);
            }
            #pragma unroll
            for (int nn = 0; nn < 4; nn++) {
                const int bc = warp_n * 32 + nn * 8 + g;
                bf[nn][0] = __float_as_uint(Bl[(kb + tg) * BSTR + bc]);
                bf[nn][1] = __float_as_uint(Bl[(kb + tg + 4) * BSTR + bc]);
            }
            #pragma unroll
            for (int mm = 0; mm < 4; mm++)
                #pragma unroll
                for (int nn = 0; nn < 4; nn++)
                    MMA_TF32(acc[mm][nn], af[mm][0], af[mm][1], af[mm][2], af[mm][3],
                             bf[nn][0], bf[nn][1]);
            #pragma unroll
            for (int nn = 0; nn < 4; nn++) {
                const int bc = warp_n * 32 + nn * 8 + g;
                bf[nn][0] = __float_as_uint(Bh[(kb + tg) * BSTR + bc]);
                bf[nn][1] = __float_as_uint(Bh[(kb + tg + 4) * BSTR + bc]);
            }
            #pragma unroll
            for (int mm = 0; mm < 4; mm++)
                #pragma unroll
                for (int nn = 0; nn < 4; nn++)
                    MMA_TF32(acc[mm][nn], af[mm][0], af[mm][1], af[mm][2], af[mm][3],
                             bf[nn][0], bf[nn][1]);
            #pragma unroll
            for (int mm = 0; mm < 4; mm++) {
                const int ar = warp_m * 64 + mm * 16 + g;
                af[mm][0] = __float_as_uint(Al[ar * ASTR + kb + tg]);
                af[mm][1] = __float_as_uint(Al[(ar + 8) * ASTR + kb + tg]);
                af[mm][2] = __float_as_uint(Al[ar * ASTR + kb + tg + 4]);
                af[mm][3] = __float_as_uint(Al[(ar + 8) * ASTR + kb + tg + 4]);
            }
            #pragma unroll
            for (int mm = 0; mm < 4; mm++)
                #pragma unroll
                for (int nn = 0; nn < 4; nn++)
                    MMA_TF32(acc[mm][nn], af[mm][0], af[mm][1], af[mm][2], af[mm][3],
                             bf[nn][0], bf[nn][1]);
        }
        __syncthreads();
    }

    #pragma unroll
    for (int nn = 0; nn < 4; nn++) {
        const int col = col0 + warp_n * 32 + nn * 8 + tg * 2;
        const float bv0 = bias[col], bv1 = bias[col + 1];
        #pragma unroll
        for (int mm = 0; mm < 4; mm++) {
            const int row = row0 + warp_m * 64 + mm * 16 + g;
            float2 o0, o1;
            if (mode == 0) {
                o0.x = fmaxf(acc[mm][nn][0] + bv0, 0.f);
                o0.y = fmaxf(acc[mm][nn][1] + bv1, 0.f);
                o1.x = fmaxf(acc[mm][nn][2] + bv0, 0.f);
                o1.y = fmaxf(acc[mm][nn][3] + bv1, 0.f);
            } else if (mode == 1) {
                o0.x = bv0 - 2.f * acc[mm][nn][0];
                o0.y = bv1 - 2.f * acc[mm][nn][1];
                o1.x = bv0 - 2.f * acc[mm][nn][2];
                o1.y = bv1 - 2.f * acc[mm][nn][3];
            } else {
                o0.x = acc[mm][nn][0] + bv0;
                o0.y = acc[mm][nn][1] + bv1;
                o1.x = acc[mm][nn][2] + bv0;
                o1.y = acc[mm][nn][3] + bv1;
            }
            *(float2*)(C + (size_t)row * N + col)       = o0;
            *(float2*)(C + (size_t)(row + 8) * N + col) = o1;
        }
    }
}

// ---------------- fallback SIMT GEMM (used only when N % 128 != 0) ----------
#define GBM 128
#define GBN 64
#define GBK 32

__global__ __launch_bounds__(256, 2) void gemm_k(
    const float* __restrict__ A, const float* __restrict__ B,
    const float* __restrict__ bias, float* __restrict__ C,
    int M, int K, int N, int mode)
{
    __shared__ float As[GBK][GBM + 4];
    __shared__ float Bs[GBK][GBN];
    const int tid  = threadIdx.x;
    const int row0 = blockIdx.y * GBM;
    const int col0 = blockIdx.x * GBN;
    const int tr = tid >> 4;
    const int tc = tid & 15;

    float acc[8][4];
    #pragma unroll
    for (int i = 0; i < 8; i++)
        #pragma unroll
        for (int j = 0; j < 4; j++) acc[i][j] = 0.f;

    const int ktiles = K / GBK;
    for (int kt = 0; kt < ktiles; kt++) {
        #pragma unroll
        for (int p = 0; p < 4; p++) {
            int lin = tid + 256 * p;
            int r = lin >> 3, q = lin & 7;
            const float4 v = *(const float4*)(A + (size_t)(row0 + r) * K + kt * GBK + q * 4);
            As[q * 4 + 0][r] = v.x; As[q * 4 + 1][r] = v.y;
            As[q * 4 + 2][r] = v.z; As[q * 4 + 3][r] = v.w;
        }
        #pragma unroll
        for (int p = 0; p < 2; p++) {
            int lin = tid + 256 * p;
            int kr = lin >> 4, j4 = lin & 15;
            *(float4*)&Bs[kr][j4 * 4] =
                *(const float4*)(B + (size_t)(kt * GBK + kr) * N + col0 + j4 * 4);
        }
        __syncthreads();
        #pragma unroll
        for (int k = 0; k < GBK; k++) {
            float a[8], b[4];
            *(float4*)&a[0] = *(const float4*)&As[k][tr * 8];
            *(float4*)&a[4] = *(const float4*)&As[k][tr * 8 + 4];
            *(float4*)&b[0] = *(const float4*)&Bs[k][tc * 4];
            #pragma unroll
            for (int i = 0; i < 8; i++)
                #pragma unroll
                for (int j = 0; j < 4; j++)
                    acc[i][j] = fmaf(a[i], b[j], acc[i][j]);
        }
        __syncthreads();
    }

    float bv[4];
    #pragma unroll
    for (int j = 0; j < 4; j++) bv[j] = bias[col0 + tc * 4 + j];

    #pragma unroll
    for (int i = 0; i < 8; i++) {
        const int row = row0 + tr * 8 + i;
        float4 o;
        o.x = fmaxf(acc[i][0] + bv[0], 0.f);
        o.y = fmaxf(acc[i][1] + bv[1], 0.f);
        o.z = fmaxf(acc[i][2] + bv[2], 0.f);
        o.w = fmaxf(acc[i][3] + bv[3], 0.f);
        *(float4*)(C + (size_t)row * N + col0 + tc * 4) = o;
    }
}

// ---------------- fusion kernels (factored first MLP layer) ------------------
// static: hid[e] = relu(eW[e] + P[src[e]] - P[dst[e]])  (eW already has bias)
__global__ __launch_bounds__(256) void static_fuse_k(
    const float* __restrict__ eW, const float* __restrict__ P,
    const void* __restrict__ ei, float* __restrict__ hid)
{
    const int e  = blockIdx.x * 4 + (threadIdx.x >> 6);
    const int c4 = threadIdx.x & 63;
    const long long s = load_ei(ei, e);
    const long long d = load_ei(ei, (long long)NE + e);
    const float4 a = *(const float4*)(eW + (size_t)e * HH + c4 * 4);
    const float4 ps = *(const float4*)(P + (size_t)s * HH + c4 * 4);
    const float4 pd = *(const float4*)(P + (size_t)d * HH + c4 * 4);
    float4 o;
    o.x = fmaxf(a.x + ps.x - pd.x, 0.f);
    o.y = fmaxf(a.y + ps.y - pd.y, 0.f);
    o.z = fmaxf(a.z + ps.z - pd.z, 0.f);
    o.w = fmaxf(a.w + ps.w - pd.w, 0.f);
    *(float4*)(hid + (size_t)e * HH + c4 * 4) = o;
}

// dynamic: hid[e=i*16+t] = relu(P1[i] - P2[i] + P2[knn[e]] + b)
__global__ __launch_bounds__(256) void dyn_fuse_k(
    const float* __restrict__ P1, const float* __restrict__ P2,
    const int* __restrict__ knn, const float* __restrict__ bias,
    float* __restrict__ hid)
{
    const int e  = blockIdx.x * 4 + (threadIdx.x >> 6);
    const int c4 = threadIdx.x & 63;
    const int i = e >> 4;
    const int j = knn[e];
    const float4 p1 = *(const float4*)(P1 + (size_t)i * HH + c4 * 4);
    const float4 pi = *(const float4*)(P2 + (size_t)i * HH + c4 * 4);
    const float4 pj = *(const float4*)(P2 + (size_t)j * HH + c4 * 4);
    const float4 b  = *(const float4*)(bias + c4 * 4);
    float4 o;
    o.x = fmaxf(p1.x - pi.x + pj.x + b.x, 0.f);
    o.y = fmaxf(p1.y - pi.y + pj.y + b.y, 0.f);
    o.z = fmaxf(p1.z - pi.z + pj.z + b.z, 0.f);
    o.w = fmaxf(p1.w - pi.w + pj.w + b.w, 0.f);
    *(float4*)(hid + (size_t)e * HH + c4 * 4) = o;
}

// ---------------- small helper kernels --------------------------------------
__global__ void scatter_add_k(float* __restrict__ agg, const float* __restrict__ m,
                              const void* __restrict__ ei)
{
    const int e = blockIdx.x, t = threadIdx.x;
    const long long d = load_ei(ei, (long long)NE + e);
    atomicAdd(&agg[d * DD + t], m[(size_t)e * DD + t]);
}

__global__ void rownorm_k(const float* __restrict__ x, float* __restrict__ sq)
{
    const int row  = blockIdx.x * 8 + (threadIdx.x >> 5);
    const int lane = threadIdx.x & 31;
    const float* p = x + (size_t)row * DD;
    float s = 0.f;
    #pragma unroll
    for (int q = 0; q < 4; q++) { float v = p[lane + 32 * q]; s = fmaf(v, v, s); }
    #pragma unroll
    for (int o = 16; o > 0; o >>= 1) s += __shfl_xor_sync(0xffffffffu, s, o);
    if (lane == 0) sq[row] = s;
}

__global__ void transpose_k(const float* __restrict__ in, float* __restrict__ out)
{
    __shared__ float t[32][33];
    const int j0 = blockIdx.x * 32, k0 = blockIdx.y * 32;
    for (int r = threadIdx.y; r < 32; r += 8)
        t[r][threadIdx.x] = in[(size_t)(j0 + r) * DD + k0 + threadIdx.x];
    __syncthreads();
    for (int r = threadIdx.y; r < 32; r += 8)
        out[(size_t)(k0 + r) * NN + j0 + threadIdx.x] = t[threadIdx.x][r];
}

__global__ __launch_bounds__(256) void topk_k(const float* __restrict__ dist,
                                              int* __restrict__ knn)
{
    __shared__ float sd[256 * 16];
    __shared__ int   si[256 * 16];
    const int i = blockIdx.x, t = threadIdx.x;
    const float* row = dist + (size_t)i * NN;

    float ld[KK]; int li[KK];
    #pragma unroll
    for (int q = 0; q < KK; q++) { ld[q] = __int_as_float(0x7f800000); li[q] = 0x7FFFFFFF; }
    float worst = __int_as_float(0x7f800000); int worsti = 0x7FFFFFFF;

    for (int j = t; j < NN; j += 256) {
        const float r = row[j];
        if (r < worst || (r == worst && j < worsti)) {
            int p = KK - 1;
            while (p > 0) {
                const bool gt = (ld[p-1] > r) || (ld[p-1] == r && li[p-1] > j);
                if (!gt) break;
                ld[p] = ld[p-1]; li[p] = li[p-1]; p--;
            }
            ld[p] = r; li[p] = j;
            worst = ld[KK-1]; worsti = li[KK-1];
        }
    }
    #pragma unroll
    for (int q = 0; q < KK; q++) { sd[t * KK + q] = ld[q]; si[t * KK + q] = li[q]; }

    for (int s = 128; s > 0; s >>= 1) {
        __syncthreads();
        if (t < s) {
            float od[KK]; int oi[KK];
            int pa = t * KK, pb = (t + s) * KK;
            const int ea_ = pa + KK, eb_ = pb + KK;
            #pragma unroll
            for (int q = 0; q < KK; q++) {
                const float da = (pa < ea_) ? sd[pa] : __int_as_float(0x7f800000);
                const int   ia = (pa < ea_) ? si[pa] : 0x7FFFFFFF;
                const float db = (pb < eb_) ? sd[pb] : __int_as_float(0x7f800000);
                const int   ib = (pb < eb_) ? si[pb] : 0x7FFFFFFF;
                const bool ta = (da < db) || (da == db && ia < ib);
                if (ta) { od[q] = da; oi[q] = ia; pa++; }
                else    { od[q] = db; oi[q] = ib; pb++; }
            }
            #pragma unroll
            for (int q = 0; q < KK; q++) { sd[t * KK + q] = od[q]; si[t * KK + q] = oi[q]; }
        }
    }
    __syncthreads();
    if (t < KK) knn[i * KK + t] = si[t];
}

__global__ void dyn_agg_k(const float* __restrict__ m, float* __restrict__ agg)
{
    const int i = blockIdx.x, d = threadIdx.x;
    const float* p = m + (size_t)i * KK * DD + d;
    float s = 0.f;
    #pragma unroll
    for (int t = 0; t < KK; t++) s += p[t * DD];
    agg[i * DD + d] = s;
}

__global__ void concat_k(const float* __restrict__ a, const float* __restrict__ b,
                         float* __restrict__ out)
{
    const int i = blockIdx.x, c = threadIdx.x;
    out[(size_t)i * 256 + c] = (c < DD) ? a[i * DD + c] : b[i * DD + c - DD];
}

// ---------------- host orchestration ---------------------------------------
static inline void gemm(const float* A, const float* B, const float* bias, float* C,
                        int M, int K, int N, int mode)
{
    if ((N % TBN) == 0 && (M % TBM) == 0) {
        dim3 g(N / TBN, M / TBM);
        mma3_gemm_k<<<g, 256, MMA3_SMEM_BYTES>>>(A, B, bias, C, M, K, N, mode);
    } else {
        dim3 g(N / GBN, M / GBM);
        gemm_k<<<g, 256>>>(A, B, bias, C, M, K, N, mode);
    }
}

extern "C" void kernel_launch(void* const* d_in, const int* in_sizes, int n_in,
                              void* d_out, int out_size)
{
    const float* x    = (const float*)d_in[0];
    const float* ea_i = (const float*)d_in[1];
    const float* sW1  = (const float*)d_in[2];
    const float* sb1  = (const float*)d_in[3];
    const float* sW2  = (const float*)d_in[4];
    const float* sb2  = (const float*)d_in[5];
    const float* uW1  = (const float*)d_in[6];
    const float* ub1  = (const float*)d_in[7];
    const float* uW2  = (const float*)d_in[8];
    const float* ub2  = (const float*)d_in[9];
    const float* rW   = (const float*)d_in[10];
    const float* rb   = (const float*)d_in[11];
    const float* dW1  = (const float*)d_in[12];
    const float* db1  = (const float*)d_in[13];
    const float* dW2  = (const float*)d_in[14];
    const float* db2  = (const float*)d_in[15];
    const float* dUW1 = (const float*)d_in[16];
    const float* dUb1 = (const float*)d_in[17];
    const float* dUW2 = (const float*)d_in[18];
    const float* dUb2 = (const float*)d_in[19];
    const float* fW1  = (const float*)d_in[20];
    const float* fb1  = (const float*)d_in[21];
    const float* fW2  = (const float*)d_in[22];
    const float* fb2  = (const float*)d_in[23];
    const void*  ei   = d_in[24];

    cudaFuncSetAttribute(mma3_gemm_k, cudaFuncAttributeMaxDynamicSharedMemorySize,
                         MMA3_SMEM_BYTES);

    float *msg, *hid, *m, *ea0, *ea1, *xs0, *xs1, *xd0, *xd1;
    float *agg, *tmpN, *P2, *cat, *sq, *xT, *dist, *zero;
    int   *knn;
    cudaGetSymbolAddress((void**)&msg,  g_msg);
    cudaGetSymbolAddress((void**)&hid,  g_hid);
    cudaGetSymbolAddress((void**)&m,    g_m);
    cudaGetSymbolAddress((void**)&ea0,  g_ea0);
    cudaGetSymbolAddress((void**)&ea1,  g_ea1);
    cudaGetSymbolAddress((void**)&xs0,  g_xs0);
    cudaGetSymbolAddress((void**)&xs1,  g_xs1);
    cudaGetSymbolAddress((void**)&xd0,  g_xd0);
    cudaGetSymbolAddress((void**)&xd1,  g_xd1);
    cudaGetSymbolAddress((void**)&agg,  g_agg);
    cudaGetSymbolAddress((void**)&tmpN, g_tmpN);
    cudaGetSymbolAddress((void**)&P2,   g_P2);
    cudaGetSymbolAddress((void**)&cat,  g_cat);
    cudaGetSymbolAddress((void**)&sq,   g_sq);
    cudaGetSymbolAddress((void**)&xT,   g_xT);
    cudaGetSymbolAddress((void**)&dist, g_dist);
    cudaGetSymbolAddress((void**)&zero, g_zero);
    cudaGetSymbolAddress((void**)&knn,  g_knn);

    detect_ei_k<<<1, 1>>>(ei);

    // ---------------- static branch: 3 conv layers + 2 edge refiners --------
    // msg@sW1 factored: ea@W_e (rows 0..63, +sb1) + (xs@W_x)[src] - (xs@W_x)[dst]
    const float* xs_in = x;
    const float* ea_in = ea_i;
    float* xs_bufs[2] = { xs0, xs1 };
    float* ea_bufs[2] = { ea0, ea1 };
    for (int i = 0; i < 3; i++) {
        const float* W1 = sW1 + (size_t)i * 192 * HH;
        gemm(ea_in, W1, sb1 + i * HH, hid, NE, DE, HH, 2);              // eW + b1
        gemm(xs_in, W1 + (size_t)DE * HH, zero, tmpN, NN, DD, HH, 2);   // P = xs@W_x
        static_fuse_k<<<NE / 4, 256>>>(hid, tmpN, ei, msg);
        gemm(msg, sW2 + (size_t)i * HH * DD, sb2 + i * DD, m, NE, HH, DD, 0);
        cudaMemsetAsync(agg, 0, (size_t)NN * DD * sizeof(float));
        scatter_add_k<<<NE, DD>>>(agg, m, ei);
        gemm(agg,  uW1 + (size_t)i * DD * HH, ub1 + i * HH, tmpN, NN, DD, HH, 0);
        float* xs_out = xs_bufs[i & 1];
        gemm(tmpN, uW2 + (size_t)i * HH * DD, ub2 + i * DD, xs_out, NN, HH, DD, 0);
        if (i < 2) {
            float* ea_out = ea_bufs[i & 1];
            gemm(ea_in, rW + (size_t)i * DE * DE, rb + i * DE, ea_out, NE, DE, DE, 0);
            ea_in = ea_out;
        }
        xs_in = xs_out;
    }

    // ---------------- dynamic branch: 2 kNN conv layers ---------------------
    // [xi | xj-xi]@dW1 factored: (xd@W_top)[i] - (xd@W_bot)[i] + (xd@W_bot)[j]
    const float* xd_in = x;
    float* xd_bufs[2] = { xd0, xd1 };
    for (int i = 0; i < 2; i++) {
        rownorm_k<<<NN / 8, 256>>>(xd_in, sq);
        transpose_k<<<dim3(NN / 32, DD / 32), dim3(32, 8)>>>(xd_in, xT);
        gemm(xd_in, xT, sq, dist, NN, DD, NN, 1);
        topk_k<<<NN, 256>>>(dist, knn);
        const float* W1 = dW1 + (size_t)i * 2 * DD * HH;
        gemm(xd_in, W1, zero, tmpN, NN, DD, HH, 2);                     // P1 = xd@W_top
        gemm(xd_in, W1 + (size_t)DD * HH, zero, P2, NN, DD, HH, 2);     // P2 = xd@W_bot
        dyn_fuse_k<<<NE / 4, 256>>>(tmpN, P2, knn, db1 + i * HH, msg);
        gemm(msg, dW2 + (size_t)i * HH * DD, db2 + i * DD, m, NE, HH, DD, 0);
        dyn_agg_k<<<NN, DD>>>(m, agg);
        gemm(agg,  dUW1 + (size_t)i * DD * HH, dUb1 + i * HH, tmpN, NN, DD, HH, 0);
        float* xd_out = xd_bufs[i];
        gemm(tmpN, dUW2 + (size_t)i * HH * DD, dUb2 + i * DD, xd_out, NN, HH, DD, 0);
        xd_in = xd_out;
    }

    // ---------------- fuse ---------------------------------------------------
    concat_k<<<NN, 256>>>(xs_in, xd_in, cat);
    gemm(cat,  fW1, fb1, tmpN, NN, 2 * DD, HH, 0);
    gemm(tmpN, fW2, fb2, (float*)d_out, NN, HH, DD, 0);
}

// round 8
// speedup vs baseline: 1.4865x; 1.0320x over previous
#include <cuda_runtime.h>
#include <cstdint>
#include <cstddef>

// ---------------- problem constants (fixed by the dataset) ----------------
#define NN   16384      // nodes
#define NE   262144     // static edges (== NN * 16, also dynamic edge count)
#define DD   128        // node dim
#define DE   64         // edge dim
#define HH   256        // hidden
#define KK   16         // kNN

// ---------------- device scratch (allocation-free rule: __device__ globals) ----
__device__ float g_msg [(size_t)NE * 256];
__device__ float g_hid [(size_t)NE * 256];
__device__ float g_ea0 [(size_t)NE * DE];
__device__ float g_ea1 [(size_t)NE * DE];
__device__ float g_xs0 [NN * DD];
__device__ float g_xs1 [NN * DD];
__device__ float g_xd0 [NN * DD];
__device__ float g_xd1 [NN * DD];
__device__ float g_agg [NN * DD];
__device__ float g_tmpN[NN * HH];
__device__ float g_P2  [NN * HH];
__device__ float g_cat [NN * 2 * DD];
__device__ float g_sq  [NN];
__device__ float g_xT  [(size_t)DD * NN];
__device__ float g_dist[(size_t)NN * NN];
__device__ int   g_knn [NN * KK];
__device__ float g_zero[HH];          // zero-initialized bias
__device__ int   g_ei64flag;

// ---------------- edge_index dtype handling (int64 vs silently-int32) -----
__global__ void detect_ei_k(const void* p) {
    const unsigned long long* q = (const unsigned long long*)p;
    int ok = 1;
    #pragma unroll
    for (int i = 0; i < 8; i++)
        if (q[i] >= (unsigned long long)NN) ok = 0;
    g_ei64flag = ok;
}

__device__ __forceinline__ long long load_ei(const void* p, long long idx) {
    if (g_ei64flag) return ((const long long*)p)[idx];
    return (long long)((const int*)p)[idx];
}

// ---------------- tf32 helpers ----------------------------------------------
__device__ __forceinline__ float f2tf(float x) {
    uint32_t u;
    asm("cvt.rna.tf32.f32 %0, %1;" : "=r"(u) : "f"(x));
    return __uint_as_float(u);
}

#define MMA_TF32(acc, a0, a1, a2, a3, b0, b1)                                  \
    asm volatile(                                                              \
        "mma.sync.aligned.m16n8k8.row.col.f32.tf32.tf32.f32 "                  \
        "{%0,%1,%2,%3}, {%4,%5,%6,%7}, {%8,%9}, {%0,%1,%2,%3};"                \
        : "+f"(acc[0]), "+f"(acc[1]), "+f"(acc[2]), "+f"(acc[3])               \
        : "r"(a0), "r"(a1), "r"(a2), "r"(a3), "r"(b0), "r"(b1))

// ---------------- 3xTF32 tensor-core GEMM (fp32-accurate) --------------------
// C = epi(A[MxK] @ B[KxN] + bias).  Requires M%128==0, N%128==0, K%32==0.
// mode 0: relu(acc+bias) store
// mode 1: bias - 2*acc store (knn distances)
// mode 2: acc+bias store
// mode 3: relu(acc+bias) atomicAdd into C[ei[NE+row]*N + col]   (static scatter)
// mode 4: relu(acc+bias) atomicAdd into C[(row>>4)*N + col]     (dynamic agg)
// Register-prefetch double buffering hides global-load latency.
#define TBM 128
#define TBN 128
#define TBK 32
#define ASTR 36
#define BSTR 136
#define A_SZ (TBM * ASTR)
#define B_SZ (TBK * BSTR)
#define MMA3_SMEM_BYTES ((2 * A_SZ + 2 * B_SZ) * 4)   // 71680 B

__global__ __launch_bounds__(256, 2) void mma3_gemm_k(
    const float* __restrict__ A, const float* __restrict__ B,
    const float* __restrict__ bias, float* __restrict__ C,
    int M, int K, int N, int mode, const void* __restrict__ ei)
{
    extern __shared__ float sm[];
    float* Ah = sm;
    float* Al = sm + A_SZ;
    float* Bh = sm + 2 * A_SZ;
    float* Bl = sm + 2 * A_SZ + B_SZ;

    const int tid  = threadIdx.x;
    const int lane = tid & 31;
    const int warp = tid >> 5;
    const int warp_m = warp & 1;
    const int warp_n = warp >> 1;
    const int row0 = blockIdx.y * TBM;
    const int col0 = blockIdx.x * TBN;
    const int g  = lane >> 2;
    const int tg = lane & 3;

    // per-thread load coordinates
    const int ar_ = tid >> 3, ac4 = tid & 7;    // A: rows ar_+32p, cols ac4*4
    const int bkr = tid >> 5, bc4 = tid & 31;   // B: krows bkr+8p, cols bc4*4

    float acc[4][4][4];
    #pragma unroll
    for (int mm = 0; mm < 4; mm++)
        #pragma unroll
        for (int nn = 0; nn < 4; nn++)
            #pragma unroll
            for (int r = 0; r < 4; r++) acc[mm][nn][r] = 0.f;

    const int ktiles = K / TBK;

    // prefetch tile 0
    float4 pa[4], pb[4];
    #pragma unroll
    for (int p = 0; p < 4; p++)
        pa[p] = *(const float4*)(A + (size_t)(row0 + ar_ + 32 * p) * K + ac4 * 4);
    #pragma unroll
    for (int p = 0; p < 4; p++)
        pb[p] = *(const float4*)(B + (size_t)(bkr + 8 * p) * N + col0 + bc4 * 4);

    for (int kt = 0; kt < ktiles; kt++) {
        // convert + store the prefetched tile
        #pragma unroll
        for (int p = 0; p < 4; p++) {
            const float4 v = pa[p];
            float4 vh, vl;
            vh.x = f2tf(v.x); vl.x = f2tf(v.x - vh.x);
            vh.y = f2tf(v.y); vl.y = f2tf(v.y - vh.y);
            vh.z = f2tf(v.z); vl.z = f2tf(v.z - vh.z);
            vh.w = f2tf(v.w); vl.w = f2tf(v.w - vh.w);
            *(float4*)&Ah[(ar_ + 32 * p) * ASTR + ac4 * 4] = vh;
            *(float4*)&Al[(ar_ + 32 * p) * ASTR + ac4 * 4] = vl;
        }
        #pragma unroll
        for (int p = 0; p < 4; p++) {
            const float4 v = pb[p];
            float4 vh, vl;
            vh.x = f2tf(v.x); vl.x = f2tf(v.x - vh.x);
            vh.y = f2tf(v.y); vl.y = f2tf(v.y - vh.y);
            vh.z = f2tf(v.z); vl.z = f2tf(v.z - vh.z);
            vh.w = f2tf(v.w); vl.w = f2tf(v.w - vh.w);
            *(float4*)&Bh[(bkr + 8 * p) * BSTR + bc4 * 4] = vh;
            *(float4*)&Bl[(bkr + 8 * p) * BSTR + bc4 * 4] = vl;
        }
        __syncthreads();

        // issue prefetch for next tile (overlaps the MMA section below)
        if (kt + 1 < ktiles) {
            const int ko = (kt + 1) * TBK;
            #pragma unroll
            for (int p = 0; p < 4; p++)
                pa[p] = *(const float4*)(A + (size_t)(row0 + ar_ + 32 * p) * K + ko + ac4 * 4);
            #pragma unroll
            for (int p = 0; p < 4; p++)
                pb[p] = *(const float4*)(B + (size_t)(ko + bkr + 8 * p) * N + col0 + bc4 * 4);
        }

        #pragma unroll
        for (int kk = 0; kk < 4; kk++) {
            const int kb = kk * 8;
            uint32_t af[4][4], bf[4][2];

            #pragma unroll
            for (int mm = 0; mm < 4; mm++) {
                const int ar = warp_m * 64 + mm * 16 + g;
                af[mm][0] = __float_as_uint(Ah[ar * ASTR + kb + tg]);
                af[mm][1] = __float_as_uint(Ah[(ar + 8) * ASTR + kb + tg]);
                af[mm][2] = __float_as_uint(Ah[ar * ASTR + kb + tg + 4]);
                af[mm][3] = __float_as_uint(Ah[(ar + 8) * ASTR + kb + tg + 4]);
            }
            #pragma unroll
            for (int nn = 0; nn < 4; nn++) {
                const int bc = warp_n * 32 + nn * 8 + g;
                bf[nn][0] = __float_as_uint(Bl[(kb + tg) * BSTR + bc]);
                bf[nn][1] = __float_as_uint(Bl[(kb + tg + 4) * BSTR + bc]);
            }
            #pragma unroll
            for (int mm = 0; mm < 4; mm++)
                #pragma unroll
                for (int nn = 0; nn < 4; nn++)
                    MMA_TF32(acc[mm][nn], af[mm][0], af[mm][1], af[mm][2], af[mm][3],
                             bf[nn][0], bf[nn][1]);
            #pragma unroll
            for (int nn = 0; nn < 4; nn++) {
                const int bc = warp_n * 32 + nn * 8 + g;
                bf[nn][0] = __float_as_uint(Bh[(kb + tg) * BSTR + bc]);
                bf[nn][1] = __float_as_uint(Bh[(kb + tg + 4) * BSTR + bc]);
            }
            #pragma unroll
            for (int mm = 0; mm < 4; mm++)
                #pragma unroll
                for (int nn = 0; nn < 4; nn++)
                    MMA_TF32(acc[mm][nn], af[mm][0], af[mm][1], af[mm][2], af[mm][3],
                             bf[nn][0], bf[nn][1]);
            #pragma unroll
            for (int mm = 0; mm < 4; mm++) {
                const int ar = warp_m * 64 + mm * 16 + g;
                af[mm][0] = __float_as_uint(Al[ar * ASTR + kb + tg]);
                af[mm][1] = __float_as_uint(Al[(ar + 8) * ASTR + kb + tg]);
                af[mm][2] = __float_as_uint(Al[ar * ASTR + kb + tg + 4]);
                af[mm][3] = __float_as_uint(Al[(ar + 8) * ASTR + kb + tg + 4]);
            }
            #pragma unroll
            for (int mm = 0; mm < 4; mm++)
                #pragma unroll
                for (int nn = 0; nn < 4; nn++)
                    MMA_TF32(acc[mm][nn], af[mm][0], af[mm][1], af[mm][2], af[mm][3],
                             bf[nn][0], bf[nn][1]);
        }
        __syncthreads();
    }

    // ---- epilogue ----
    if (mode <= 2) {
        #pragma unroll
        for (int nn = 0; nn < 4; nn++) {
            const int col = col0 + warp_n * 32 + nn * 8 + tg * 2;
            const float bv0 = bias[col], bv1 = bias[col + 1];
            #pragma unroll
            for (int mm = 0; mm < 4; mm++) {
                const int row = row0 + warp_m * 64 + mm * 16 + g;
                float2 o0, o1;
                if (mode == 0) {
                    o0.x = fmaxf(acc[mm][nn][0] + bv0, 0.f);
                    o0.y = fmaxf(acc[mm][nn][1] + bv1, 0.f);
                    o1.x = fmaxf(acc[mm][nn][2] + bv0, 0.f);
                    o1.y = fmaxf(acc[mm][nn][3] + bv1, 0.f);
                } else if (mode == 1) {
                    o0.x = bv0 - 2.f * acc[mm][nn][0];
                    o0.y = bv1 - 2.f * acc[mm][nn][1];
                    o1.x = bv0 - 2.f * acc[mm][nn][2];
                    o1.y = bv1 - 2.f * acc[mm][nn][3];
                } else {
                    o0.x = acc[mm][nn][0] + bv0;
                    o0.y = acc[mm][nn][1] + bv1;
                    o1.x = acc[mm][nn][2] + bv0;
                    o1.y = acc[mm][nn][3] + bv1;
                }
                *(float2*)(C + (size_t)row * N + col)       = o0;
                *(float2*)(C + (size_t)(row + 8) * N + col) = o1;
            }
        }
    } else {
        // relu + scatter-add
        #pragma unroll
        for (int mm = 0; mm < 4; mm++) {
            const int row = row0 + warp_m * 64 + mm * 16 + g;
            long long d0, d1;
            if (mode == 3) {
                d0 = load_ei(ei, (long long)NE + row);
                d1 = load_ei(ei, (long long)NE + row + 8);
            } else {
                d0 = row >> 4;
                d1 = (row + 8) >> 4;
            }
            #pragma unroll
            for (int nn = 0; nn < 4; nn++) {
                const int col = col0 + warp_n * 32 + nn * 8 + tg * 2;
                const float bv0 = bias[col], bv1 = bias[col + 1];
                atomicAdd(&C[d0 * N + col],     fmaxf(acc[mm][nn][0] + bv0, 0.f));
                atomicAdd(&C[d0 * N + col + 1], fmaxf(acc[mm][nn][1] + bv1, 0.f));
                atomicAdd(&C[d1 * N + col],     fmaxf(acc[mm][nn][2] + bv0, 0.f));
                atomicAdd(&C[d1 * N + col + 1], fmaxf(acc[mm][nn][3] + bv1, 0.f));
            }
        }
    }
}

// ---------------- fallback SIMT GEMM (used only when N % 128 != 0) ----------
#define GBM 128
#define GBN 64
#define GBK 32

__global__ __launch_bounds__(256, 2) void gemm_k(
    const float* __restrict__ A, const float* __restrict__ B,
    const float* __restrict__ bias, float* __restrict__ C,
    int M, int K, int N, int mode)
{
    __shared__ float As[GBK][GBM + 4];
    __shared__ float Bs[GBK][GBN];
    const int tid  = threadIdx.x;
    const int row0 = blockIdx.y * GBM;
    const int col0 = blockIdx.x * GBN;
    const int tr = tid >> 4;
    const int tc = tid & 15;

    float acc[8][4];
    #pragma unroll
    for (int i = 0; i < 8; i++)
        #pragma unroll
        for (int j = 0; j < 4; j++) acc[i][j] = 0.f;

    const int ktiles = K / GBK;
    for (int kt = 0; kt < ktiles; kt++) {
        #pragma unroll
        for (int p = 0; p < 4; p++) {
            int lin = tid + 256 * p;
            int r = lin >> 3, q = lin & 7;
            const float4 v = *(const float4*)(A + (size_t)(row0 + r) * K + kt * GBK + q * 4);
            As[q * 4 + 0][r] = v.x; As[q * 4 + 1][r] = v.y;
            As[q * 4 + 2][r] = v.z; As[q * 4 + 3][r] = v.w;
        }
        #pragma unroll
        for (int p = 0; p < 2; p++) {
            int lin = tid + 256 * p;
            int kr = lin >> 4, j4 = lin & 15;
            *(float4*)&Bs[kr][j4 * 4] =
                *(const float4*)(B + (size_t)(kt * GBK + kr) * N + col0 + j4 * 4);
        }
        __syncthreads();
        #pragma unroll
        for (int k = 0; k < GBK; k++) {
            float a[8], b[4];
            *(float4*)&a[0] = *(const float4*)&As[k][tr * 8];
            *(float4*)&a[4] = *(const float4*)&As[k][tr * 8 + 4];
            *(float4*)&b[0] = *(const float4*)&Bs[k][tc * 4];
            #pragma unroll
            for (int i = 0; i < 8; i++)
                #pragma unroll
                for (int j = 0; j < 4; j++)
                    acc[i][j] = fmaf(a[i], b[j], acc[i][j]);
        }
        __syncthreads();
    }

    float bv[4];
    #pragma unroll
    for (int j = 0; j < 4; j++) bv[j] = bias[col0 + tc * 4 + j];

    #pragma unroll
    for (int i = 0; i < 8; i++) {
        const int row = row0 + tr * 8 + i;
        float4 o;
        o.x = fmaxf(acc[i][0] + bv[0], 0.f);
        o.y = fmaxf(acc[i][1] + bv[1], 0.f);
        o.z = fmaxf(acc[i][2] + bv[2], 0.f);
        o.w = fmaxf(acc[i][3] + bv[3], 0.f);
        *(float4*)(C + (size_t)row * N + col0 + tc * 4) = o;
    }
}

// ---------------- fusion kernels (factored first MLP layer) ------------------
// static: hid[e] = relu(eW[e] + P[src[e]] - P[dst[e]])  (eW already has bias)
__global__ __launch_bounds__(256) void static_fuse_k(
    const float* __restrict__ eW, const float* __restrict__ P,
    const void* __restrict__ ei, float* __restrict__ hid)
{
    const int e  = blockIdx.x * 4 + (threadIdx.x >> 6);
    const int c4 = threadIdx.x & 63;
    const long long s = load_ei(ei, e);
    const long long d = load_ei(ei, (long long)NE + e);
    const float4 a = *(const float4*)(eW + (size_t)e * HH + c4 * 4);
    const float4 ps = *(const float4*)(P + (size_t)s * HH + c4 * 4);
    const float4 pd = *(const float4*)(P + (size_t)d * HH + c4 * 4);
    float4 o;
    o.x = fmaxf(a.x + ps.x - pd.x, 0.f);
    o.y = fmaxf(a.y + ps.y - pd.y, 0.f);
    o.z = fmaxf(a.z + ps.z - pd.z, 0.f);
    o.w = fmaxf(a.w + ps.w - pd.w, 0.f);
    *(float4*)(hid + (size_t)e * HH + c4 * 4) = o;
}

// dynamic: hid[e=i*16+t] = relu(P1[i] - P2[i] + P2[knn[e]] + b)
__global__ __launch_bounds__(256) void dyn_fuse_k(
    const float* __restrict__ P1, const float* __restrict__ P2,
    const int* __restrict__ knn, const float* __restrict__ bias,
    float* __restrict__ hid)
{
    const int e  = blockIdx.x * 4 + (threadIdx.x >> 6);
    const int c4 = threadIdx.x & 63;
    const int i = e >> 4;
    const int j = knn[e];
    const float4 p1 = *(const float4*)(P1 + (size_t)i * HH + c4 * 4);
    const float4 pi = *(const float4*)(P2 + (size_t)i * HH + c4 * 4);
    const float4 pj = *(const float4*)(P2 + (size_t)j * HH + c4 * 4);
    const float4 b  = *(const float4*)(bias + c4 * 4);
    float4 o;
    o.x = fmaxf(p1.x - pi.x + pj.x + b.x, 0.f);
    o.y = fmaxf(p1.y - pi.y + pj.y + b.y, 0.f);
    o.z = fmaxf(p1.z - pi.z + pj.z + b.z, 0.f);
    o.w = fmaxf(p1.w - pi.w + pj.w + b.w, 0.f);
    *(float4*)(hid + (size_t)e * HH + c4 * 4) = o;
}

// ---------------- small helper kernels --------------------------------------
__global__ void rownorm_k(const float* __restrict__ x, float* __restrict__ sq)
{
    const int row  = blockIdx.x * 8 + (threadIdx.x >> 5);
    const int lane = threadIdx.x & 31;
    const float* p = x + (size_t)row * DD;
    float s = 0.f;
    #pragma unroll
    for (int q = 0; q < 4; q++) { float v = p[lane + 32 * q]; s = fmaf(v, v, s); }
    #pragma unroll
    for (int o = 16; o > 0; o >>= 1) s += __shfl_xor_sync(0xffffffffu, s, o);
    if (lane == 0) sq[row] = s;
}

__global__ void transpose_k(const float* __restrict__ in, float* __restrict__ out)
{
    __shared__ float t[32][33];
    const int j0 = blockIdx.x * 32, k0 = blockIdx.y * 32;
    for (int r = threadIdx.y; r < 32; r += 8)
        t[r][threadIdx.x] = in[(size_t)(j0 + r) * DD + k0 + threadIdx.x];
    __syncthreads();
    for (int r = threadIdx.y; r < 32; r += 8)
        out[(size_t)(k0 + r) * NN + j0 + threadIdx.x] = t[threadIdx.x][r];
}

__global__ __launch_bounds__(256) void topk_k(const float* __restrict__ dist,
                                              int* __restrict__ knn)
{
    __shared__ float sd[256 * 16];
    __shared__ int   si[256 * 16];
    const int i = blockIdx.x, t = threadIdx.x;
    const float* row = dist + (size_t)i * NN;

    float ld[KK]; int li[KK];
    #pragma unroll
    for (int q = 0; q < KK; q++) { ld[q] = __int_as_float(0x7f800000); li[q] = 0x7FFFFFFF; }
    float worst = __int_as_float(0x7f800000); int worsti = 0x7FFFFFFF;

    for (int j = t; j < NN; j += 256) {
        const float r = row[j];
        if (r < worst || (r == worst && j < worsti)) {
            int p = KK - 1;
            while (p > 0) {
                const bool gt = (ld[p-1] > r) || (ld[p-1] == r && li[p-1] > j);
                if (!gt) break;
                ld[p] = ld[p-1]; li[p] = li[p-1]; p--;
            }
            ld[p] = r; li[p] = j;
            worst = ld[KK-1]; worsti = li[KK-1];
        }
    }
    #pragma unroll
    for (int q = 0; q < KK; q++) { sd[t * KK + q] = ld[q]; si[t * KK + q] = li[q]; }

    for (int s = 128; s > 0; s >>= 1) {
        __syncthreads();
        if (t < s) {
            float od[KK]; int oi[KK];
            int pa = t * KK, pb = (t + s) * KK;
            const int ea_ = pa + KK, eb_ = pb + KK;
            #pragma unroll
            for (int q = 0; q < KK; q++) {
                const float da = (pa < ea_) ? sd[pa] : __int_as_float(0x7f800000);
                const int   ia = (pa < ea_) ? si[pa] : 0x7FFFFFFF;
                const float db = (pb < eb_) ? sd[pb] : __int_as_float(0x7f800000);
                const int   ib = (pb < eb_) ? si[pb] : 0x7FFFFFFF;
                const bool ta = (da < db) || (da == db && ia < ib);
                if (ta) { od[q] = da; oi[q] = ia; pa++; }
                else    { od[q] = db; oi[q] = ib; pb++; }
            }
            #pragma unroll
            for (int q = 0; q < KK; q++) { sd[t * KK + q] = od[q]; si[t * KK + q] = oi[q]; }
        }
    }
    __syncthreads();
    if (t < KK) knn[i * KK + t] = si[t];
}

__global__ void concat_k(const float* __restrict__ a, const float* __restrict__ b,
                         float* __restrict__ out)
{
    const int i = blockIdx.x, c = threadIdx.x;
    out[(size_t)i * 256 + c] = (c < DD) ? a[i * DD + c] : b[i * DD + c - DD];
}

// ---------------- host orchestration ---------------------------------------
static inline void gemm(const float* A, const float* B, const float* bias, float* C,
                        int M, int K, int N, int mode, const void* ei = nullptr)
{
    if ((N % TBN) == 0 && (M % TBM) == 0) {
        dim3 g(N / TBN, M / TBM);
        mma3_gemm_k<<<g, 256, MMA3_SMEM_BYTES>>>(A, B, bias, C, M, K, N, mode, ei);
    } else {
        dim3 g(N / GBN, M / GBM);
        gemm_k<<<g, 256>>>(A, B, bias, C, M, K, N, mode);
    }
}

extern "C" void kernel_launch(void* const* d_in, const int* in_sizes, int n_in,
                              void* d_out, int out_size)
{
    const float* x    = (const float*)d_in[0];
    const float* ea_i = (const float*)d_in[1];
    const float* sW1  = (const float*)d_in[2];
    const float* sb1  = (const float*)d_in[3];
    const float* sW2  = (const float*)d_in[4];
    const float* sb2  = (const float*)d_in[5];
    const float* uW1  = (const float*)d_in[6];
    const float* ub1  = (const float*)d_in[7];
    const float* uW2  = (const float*)d_in[8];
    const float* ub2  = (const float*)d_in[9];
    const float* rW   = (const float*)d_in[10];
    const float* rb   = (const float*)d_in[11];
    const float* dW1  = (const float*)d_in[12];
    const float* db1  = (const float*)d_in[13];
    const float* dW2  = (const float*)d_in[14];
    const float* db2  = (const float*)d_in[15];
    const float* dUW1 = (const float*)d_in[16];
    const float* dUb1 = (const float*)d_in[17];
    const float* dUW2 = (const float*)d_in[18];
    const float* dUb2 = (const float*)d_in[19];
    const float* fW1  = (const float*)d_in[20];
    const float* fb1  = (const float*)d_in[21];
    const float* fW2  = (const float*)d_in[22];
    const float* fb2  = (const float*)d_in[23];
    const void*  ei   = d_in[24];

    cudaFuncSetAttribute(mma3_gemm_k, cudaFuncAttributeMaxDynamicSharedMemorySize,
                         MMA3_SMEM_BYTES);

    float *msg, *hid, *ea0, *ea1, *xs0, *xs1, *xd0, *xd1;
    float *agg, *tmpN, *P2, *cat, *sq, *xT, *dist, *zero;
    int   *knn;
    cudaGetSymbolAddress((void**)&msg,  g_msg);
    cudaGetSymbolAddress((void**)&hid,  g_hid);
    cudaGetSymbolAddress((void**)&ea0,  g_ea0);
    cudaGetSymbolAddress((void**)&ea1,  g_ea1);
    cudaGetSymbolAddress((void**)&xs0,  g_xs0);
    cudaGetSymbolAddress((void**)&xs1,  g_xs1);
    cudaGetSymbolAddress((void**)&xd0,  g_xd0);
    cudaGetSymbolAddress((void**)&xd1,  g_xd1);
    cudaGetSymbolAddress((void**)&agg,  g_agg);
    cudaGetSymbolAddress((void**)&tmpN, g_tmpN);
    cudaGetSymbolAddress((void**)&P2,   g_P2);
    cudaGetSymbolAddress((void**)&cat,  g_cat);
    cudaGetSymbolAddress((void**)&sq,   g_sq);
    cudaGetSymbolAddress((void**)&xT,   g_xT);
    cudaGetSymbolAddress((void**)&dist, g_dist);
    cudaGetSymbolAddress((void**)&zero, g_zero);
    cudaGetSymbolAddress((void**)&knn,  g_knn);

    detect_ei_k<<<1, 1>>>(ei);

    // ---------------- static branch: 3 conv layers + 2 edge refiners --------
    // msg@sW1 factored: ea@W_e (+sb1) + (xs@W_x)[src] - (xs@W_x)[dst]
    const float* xs_in = x;
    const float* ea_in = ea_i;
    float* xs_bufs[2] = { xs0, xs1 };
    float* ea_bufs[2] = { ea0, ea1 };
    for (int i = 0; i < 3; i++) {
        const float* W1 = sW1 + (size_t)i * 192 * HH;
        gemm(ea_in, W1, sb1 + i * HH, hid, NE, DE, HH, 2);              // eW + b1
        gemm(xs_in, W1 + (size_t)DE * HH, zero, tmpN, NN, DD, HH, 2);   // P = xs@W_x
        static_fuse_k<<<NE / 4, 256>>>(hid, tmpN, ei, msg);
        cudaMemsetAsync(agg, 0, (size_t)NN * DD * sizeof(float));
        gemm(msg, sW2 + (size_t)i * HH * DD, sb2 + i * DD, agg, NE, HH, DD, 3, ei);
        gemm(agg,  uW1 + (size_t)i * DD * HH, ub1 + i * HH, tmpN, NN, DD, HH, 0);
        float* xs_out = xs_bufs[i & 1];
        gemm(tmpN, uW2 + (size_t)i * HH * DD, ub2 + i * DD, xs_out, NN, HH, DD, 0);
        if (i < 2) {
            float* ea_out = ea_bufs[i & 1];
            gemm(ea_in, rW + (size_t)i * DE * DE, rb + i * DE, ea_out, NE, DE, DE, 0);
            ea_in = ea_out;
        }
        xs_in = xs_out;
    }

    // ---------------- dynamic branch: 2 kNN conv layers ---------------------
    // [xi | xj-xi]@dW1 factored: (xd@W_top)[i] - (xd@W_bot)[i] + (xd@W_bot)[j]
    const float* xd_in = x;
    float* xd_bufs[2] = { xd0, xd1 };
    for (int i = 0; i < 2; i++) {
        rownorm_k<<<NN / 8, 256>>>(xd_in, sq);
        transpose_k<<<dim3(NN / 32, DD / 32), dim3(32, 8)>>>(xd_in, xT);
        gemm(xd_in, xT, sq, dist, NN, DD, NN, 1);
        topk_k<<<NN, 256>>>(dist, knn);
        const float* W1 = dW1 + (size_t)i * 2 * DD * HH;
        gemm(xd_in, W1, zero, tmpN, NN, DD, HH, 2);                     // P1 = xd@W_top
        gemm(xd_in, W1 + (size_t)DD * HH, zero, P2, NN, DD, HH, 2);     // P2 = xd@W_bot
        dyn_fuse_k<<<NE / 4, 256>>>(tmpN, P2, knn, db1 + i * HH, msg);
        cudaMemsetAsync(agg, 0, (size_t)NN * DD * sizeof(float));
        gemm(msg, dW2 + (size_t)i * HH * DD, db2 + i * DD, agg, NE, HH, DD, 4);
        gemm(agg,  dUW1 + (size_t)i * DD * HH, dUb1 + i * HH, tmpN, NN, DD, HH, 0);
        float* xd_out = xd_bufs[i];
        gemm(tmpN, dUW2 + (size_t)i * HH * DD, dUb2 + i * DD, xd_out, NN, HH, DD, 0);
        xd_in = xd_out;
    }

    // ---------------- fuse ---------------------------------------------------
    concat_k<<<NN, 256>>>(xs_in, xd_in, cat);
    gemm(cat,  fW1, fb1, tmpN, NN, 2 * DD, HH, 0);
    gemm(tmpN, fW2, fb2, (float*)d_out, NN, HH, DD, 0);
}

// round 9
// speedup vs baseline: 1.6480x; 1.1087x over previous
#include <cuda_runtime.h>
#include <cstdint>
#include <cstddef>

// ---------------- problem constants (fixed by the dataset) ----------------
#define NN   16384      // nodes
#define NE   262144     // static edges (== NN * 16, also dynamic edge count)
#define DD   128        // node dim
#define DE   64         // edge dim
#define HH   256        // hidden
#define KK   16         // kNN

// ---------------- device scratch (allocation-free rule: __device__ globals) ----
__device__ float g_msg [(size_t)NE * 256];
__device__ float g_hid [(size_t)NE * 256];
__device__ float g_ea0 [(size_t)NE * DE];
__device__ float g_ea1 [(size_t)NE * DE];
__device__ float g_xs0 [NN * DD];
__device__ float g_xs1 [NN * DD];
__device__ float g_xd0 [NN * DD];
__device__ float g_xd1 [NN * DD];
__device__ float g_agg [NN * DD];
__device__ float g_tmpN[NN * HH];
__device__ float g_P2  [NN * HH];
__device__ float g_cat [NN * 2 * DD];
__device__ float g_sq  [NN];
__device__ float g_xT  [(size_t)DD * NN];
__device__ float g_dist[(size_t)NN * NN];
__device__ int   g_knn [NN * KK];
__device__ float g_zero[HH];          // zero-initialized bias
__device__ int   g_ei64flag;

// ---------------- edge_index dtype handling (int64 vs silently-int32) -----
__global__ void detect_ei_k(const void* p) {
    const unsigned long long* q = (const unsigned long long*)p;
    int ok = 1;
    #pragma unroll
    for (int i = 0; i < 8; i++)
        if (q[i] >= (unsigned long long)NN) ok = 0;
    g_ei64flag = ok;
}

__device__ __forceinline__ long long load_ei(const void* p, long long idx) {
    if (g_ei64flag) return ((const long long*)p)[idx];
    return (long long)((const int*)p)[idx];
}

// ---------------- tf32 helpers ----------------------------------------------
__device__ __forceinline__ float f2tf(float x) {
    uint32_t u;
    asm("cvt.rna.tf32.f32 %0, %1;" : "=r"(u) : "f"(x));
    return __uint_as_float(u);
}

#define MMA_TF32(acc, a0, a1, a2, a3, b0, b1)                                  \
    asm volatile(                                                              \
        "mma.sync.aligned.m16n8k8.row.col.f32.tf32.tf32.f32 "                  \
        "{%0,%1,%2,%3}, {%4,%5,%6,%7}, {%8,%9}, {%0,%1,%2,%3};"                \
        : "+f"(acc[0]), "+f"(acc[1]), "+f"(acc[2]), "+f"(acc[3])               \
        : "r"(a0), "r"(a1), "r"(a2), "r"(a3), "r"(b0), "r"(b1))

#define TBM 128
#define TBN 128
#define TBK 32
#define ASTR 36
#define BSTR 136
#define A_SZ (TBM * ASTR)
#define B_SZ (TBK * BSTR)
#define MMA3_SMEM_BYTES ((2 * A_SZ + 2 * B_SZ) * 4)   // 71680 B

// ---------------- 3xTF32 tensor-core GEMM (fp32-accurate) --------------------
// C = epi(A[MxK] @ B[KxN] + bias).  Requires M%128==0, N%128==0, K%32==0.
// mode 0: relu(acc+bias) store
// mode 2: acc+bias store
// mode 3: relu(acc+bias) atomicAdd into C[ei[NE+row]*N + col]   (static scatter)
// mode 4: relu(acc+bias) atomicAdd into C[(row>>4)*N + col]     (dynamic agg)
__global__ __launch_bounds__(256, 2) void mma3_gemm_k(
    const float* __restrict__ A, const float* __restrict__ B,
    const float* __restrict__ bias, float* __restrict__ C,
    int M, int K, int N, int mode, const void* __restrict__ ei)
{
    extern __shared__ float sm[];
    float* Ah = sm;
    float* Al = sm + A_SZ;
    float* Bh = sm + 2 * A_SZ;
    float* Bl = sm + 2 * A_SZ + B_SZ;

    const int tid  = threadIdx.x;
    const int lane = tid & 31;
    const int warp = tid >> 5;
    const int warp_m = warp & 1;
    const int warp_n = warp >> 1;
    const int row0 = blockIdx.y * TBM;
    const int col0 = blockIdx.x * TBN;
    const int g  = lane >> 2;
    const int tg = lane & 3;

    const int ar_ = tid >> 3, ac4 = tid & 7;
    const int bkr = tid >> 5, bc4 = tid & 31;

    float acc[4][4][4];
    #pragma unroll
    for (int mm = 0; mm < 4; mm++)
        #pragma unroll
        for (int nn = 0; nn < 4; nn++)
            #pragma unroll
            for (int r = 0; r < 4; r++) acc[mm][nn][r] = 0.f;

    const int ktiles = K / TBK;

    float4 pa[4], pb[4];
    #pragma unroll
    for (int p = 0; p < 4; p++)
        pa[p] = *(const float4*)(A + (size_t)(row0 + ar_ + 32 * p) * K + ac4 * 4);
    #pragma unroll
    for (int p = 0; p < 4; p++)
        pb[p] = *(const float4*)(B + (size_t)(bkr + 8 * p) * N + col0 + bc4 * 4);

    for (int kt = 0; kt < ktiles; kt++) {
        #pragma unroll
        for (int p = 0; p < 4; p++) {
            const float4 v = pa[p];
            float4 vh, vl;
            vh.x = f2tf(v.x); vl.x = f2tf(v.x - vh.x);
            vh.y = f2tf(v.y); vl.y = f2tf(v.y - vh.y);
            vh.z = f2tf(v.z); vl.z = f2tf(v.z - vh.z);
            vh.w = f2tf(v.w); vl.w = f2tf(v.w - vh.w);
            *(float4*)&Ah[(ar_ + 32 * p) * ASTR + ac4 * 4] = vh;
            *(float4*)&Al[(ar_ + 32 * p) * ASTR + ac4 * 4] = vl;
        }
        #pragma unroll
        for (int p = 0; p < 4; p++) {
            const float4 v = pb[p];
            float4 vh, vl;
            vh.x = f2tf(v.x); vl.x = f2tf(v.x - vh.x);
            vh.y = f2tf(v.y); vl.y = f2tf(v.y - vh.y);
            vh.z = f2tf(v.z); vl.z = f2tf(v.z - vh.z);
            vh.w = f2tf(v.w); vl.w = f2tf(v.w - vh.w);
            *(float4*)&Bh[(bkr + 8 * p) * BSTR + bc4 * 4] = vh;
            *(float4*)&Bl[(bkr + 8 * p) * BSTR + bc4 * 4] = vl;
        }
        __syncthreads();

        if (kt + 1 < ktiles) {
            const int ko = (kt + 1) * TBK;
            #pragma unroll
            for (int p = 0; p < 4; p++)
                pa[p] = *(const float4*)(A + (size_t)(row0 + ar_ + 32 * p) * K + ko + ac4 * 4);
            #pragma unroll
            for (int p = 0; p < 4; p++)
                pb[p] = *(const float4*)(B + (size_t)(ko + bkr + 8 * p) * N + col0 + bc4 * 4);
        }

        #pragma unroll
        for (int kk = 0; kk < 4; kk++) {
            const int kb = kk * 8;
            uint32_t af[4][4], bf[4][2];

            #pragma unroll
            for (int mm = 0; mm < 4; mm++) {
                const int ar = warp_m * 64 + mm * 16 + g;
                af[mm][0] = __float_as_uint(Ah[ar * ASTR + kb + tg]);
                af[mm][1] = __float_as_uint(Ah[(ar + 8) * ASTR + kb + tg]);
                af[mm][2] = __float_as_uint(Ah[ar * ASTR + kb + tg + 4]);
                af[mm][3] = __float_as_uint(Ah[(ar + 8) * ASTR + kb + tg + 4]);
            }
            #pragma unroll
            for (int nn = 0; nn < 4; nn++) {
                const int bc = warp_n * 32 + nn * 8 + g;
                bf[nn][0] = __float_as_uint(Bl[(kb + tg) * BSTR + bc]);
                bf[nn][1] = __float_as_uint(Bl[(kb + tg + 4) * BSTR + bc]);
            }
            #pragma unroll
            for (int mm = 0; mm < 4; mm++)
                #pragma unroll
                for (int nn = 0; nn < 4; nn++)
                    MMA_TF32(acc[mm][nn], af[mm][0], af[mm][1], af[mm][2], af[mm][3],
                             bf[nn][0], bf[nn][1]);
            #pragma unroll
            for (int nn = 0; nn < 4; nn++) {
                const int bc = warp_n * 32 + nn * 8 + g;
                bf[nn][0] = __float_as_uint(Bh[(kb + tg) * BSTR + bc]);
                bf[nn][1] = __float_as_uint(Bh[(kb + tg + 4) * BSTR + bc]);
            }
            #pragma unroll
            for (int mm = 0; mm < 4; mm++)
                #pragma unroll
                for (int nn = 0; nn < 4; nn++)
                    MMA_TF32(acc[mm][nn], af[mm][0], af[mm][1], af[mm][2], af[mm][3],
                             bf[nn][0], bf[nn][1]);
            #pragma unroll
            for (int mm = 0; mm < 4; mm++) {
                const int ar = warp_m * 64 + mm * 16 + g;
                af[mm][0] = __float_as_uint(Al[ar * ASTR + kb + tg]);
                af[mm][1] = __float_as_uint(Al[(ar + 8) * ASTR + kb + tg]);
                af[mm][2] = __float_as_uint(Al[ar * ASTR + kb + tg + 4]);
                af[mm][3] = __float_as_uint(Al[(ar + 8) * ASTR + kb + tg + 4]);
            }
            #pragma unroll
            for (int mm = 0; mm < 4; mm++)
                #pragma unroll
                for (int nn = 0; nn < 4; nn++)
                    MMA_TF32(acc[mm][nn], af[mm][0], af[mm][1], af[mm][2], af[mm][3],
                             bf[nn][0], bf[nn][1]);
        }
        __syncthreads();
    }

    if (mode <= 2) {
        #pragma unroll
        for (int nn = 0; nn < 4; nn++) {
            const int col = col0 + warp_n * 32 + nn * 8 + tg * 2;
            const float bv0 = bias[col], bv1 = bias[col + 1];
            #pragma unroll
            for (int mm = 0; mm < 4; mm++) {
                const int row = row0 + warp_m * 64 + mm * 16 + g;
                float2 o0, o1;
                if (mode == 0) {
                    o0.x = fmaxf(acc[mm][nn][0] + bv0, 0.f);
                    o0.y = fmaxf(acc[mm][nn][1] + bv1, 0.f);
                    o1.x = fmaxf(acc[mm][nn][2] + bv0, 0.f);
                    o1.y = fmaxf(acc[mm][nn][3] + bv1, 0.f);
                } else {
                    o0.x = acc[mm][nn][0] + bv0;
                    o0.y = acc[mm][nn][1] + bv1;
                    o1.x = acc[mm][nn][2] + bv0;
                    o1.y = acc[mm][nn][3] + bv1;
                }
                *(float2*)(C + (size_t)row * N + col)       = o0;
                *(float2*)(C + (size_t)(row + 8) * N + col) = o1;
            }
        }
    } else {
        #pragma unroll
        for (int mm = 0; mm < 4; mm++) {
            const int row = row0 + warp_m * 64 + mm * 16 + g;
            long long d0, d1;
            if (mode == 3) {
                d0 = load_ei(ei, (long long)NE + row);
                d1 = load_ei(ei, (long long)NE + row + 8);
            } else {
                d0 = row >> 4;
                d1 = (row + 8) >> 4;
            }
            #pragma unroll
            for (int nn = 0; nn < 4; nn++) {
                const int col = col0 + warp_n * 32 + nn * 8 + tg * 2;
                const float bv0 = bias[col], bv1 = bias[col + 1];
                atomicAdd(&C[d0 * N + col],     fmaxf(acc[mm][nn][0] + bv0, 0.f));
                atomicAdd(&C[d0 * N + col + 1], fmaxf(acc[mm][nn][1] + bv1, 0.f));
                atomicAdd(&C[d1 * N + col],     fmaxf(acc[mm][nn][2] + bv0, 0.f));
                atomicAdd(&C[d1 * N + col + 1], fmaxf(acc[mm][nn][3] + bv1, 0.f));
            }
        }
    }
}

// ---------------- symmetric distance GEMM (lower triangle + mirror) ----------
// dist[i][j] = sq[j] - 2 * <x_i, x_j>; computes tiles bi >= bj only and writes
// the mirrored upper-triangle tile from the same accumulators (bit-identical).
__global__ __launch_bounds__(256, 2) void dist_sym_k(
    const float* __restrict__ X, const float* __restrict__ XT,
    const float* __restrict__ sq, float* __restrict__ C)
{
    const int bi = blockIdx.y, bj = blockIdx.x;
    if (bj > bi) return;

    extern __shared__ float sm[];
    float* Ah = sm;
    float* Al = sm + A_SZ;
    float* Bh = sm + 2 * A_SZ;
    float* Bl = sm + 2 * A_SZ + B_SZ;

    const int tid  = threadIdx.x;
    const int lane = tid & 31;
    const int warp = tid >> 5;
    const int warp_m = warp & 1;
    const int warp_n = warp >> 1;
    const int row0 = bi * TBM;
    const int col0 = bj * TBM;
    const int g  = lane >> 2;
    const int tg = lane & 3;

    const int ar_ = tid >> 3, ac4 = tid & 7;
    const int bkr = tid >> 5, bc4 = tid & 31;

    float acc[4][4][4];
    #pragma unroll
    for (int mm = 0; mm < 4; mm++)
        #pragma unroll
        for (int nn = 0; nn < 4; nn++)
            #pragma unroll
            for (int r = 0; r < 4; r++) acc[mm][nn][r] = 0.f;

    float4 pa[4], pb[4];
    #pragma unroll
    for (int p = 0; p < 4; p++)
        pa[p] = *(const float4*)(X + (size_t)(row0 + ar_ + 32 * p) * DD + ac4 * 4);
    #pragma unroll
    for (int p = 0; p < 4; p++)
        pb[p] = *(const float4*)(XT + (size_t)(bkr + 8 * p) * NN + col0 + bc4 * 4);

    #pragma unroll
    for (int kt = 0; kt < DD / TBK; kt++) {
        #pragma unroll
        for (int p = 0; p < 4; p++) {
            const float4 v = pa[p];
            float4 vh, vl;
            vh.x = f2tf(v.x); vl.x = f2tf(v.x - vh.x);
            vh.y = f2tf(v.y); vl.y = f2tf(v.y - vh.y);
            vh.z = f2tf(v.z); vl.z = f2tf(v.z - vh.z);
            vh.w = f2tf(v.w); vl.w = f2tf(v.w - vh.w);
            *(float4*)&Ah[(ar_ + 32 * p) * ASTR + ac4 * 4] = vh;
            *(float4*)&Al[(ar_ + 32 * p) * ASTR + ac4 * 4] = vl;
        }
        #pragma unroll
        for (int p = 0; p < 4; p++) {
            const float4 v = pb[p];
            float4 vh, vl;
            vh.x = f2tf(v.x); vl.x = f2tf(v.x - vh.x);
            vh.y = f2tf(v.y); vl.y = f2tf(v.y - vh.y);
            vh.z = f2tf(v.z); vl.z = f2tf(v.z - vh.z);
            vh.w = f2tf(v.w); vl.w = f2tf(v.w - vh.w);
            *(float4*)&Bh[(bkr + 8 * p) * BSTR + bc4 * 4] = vh;
            *(float4*)&Bl[(bkr + 8 * p) * BSTR + bc4 * 4] = vl;
        }
        __syncthreads();

        if (kt + 1 < DD / TBK) {
            const int ko = (kt + 1) * TBK;
            #pragma unroll
            for (int p = 0; p < 4; p++)
                pa[p] = *(const float4*)(X + (size_t)(row0 + ar_ + 32 * p) * DD + ko + ac4 * 4);
            #pragma unroll
            for (int p = 0; p < 4; p++)
                pb[p] = *(const float4*)(XT + (size_t)(ko + bkr + 8 * p) * NN + col0 + bc4 * 4);
        }

        #pragma unroll
        for (int kk = 0; kk < 4; kk++) {
            const int kb = kk * 8;
            uint32_t af[4][4], bf[4][2];

            #pragma unroll
            for (int mm = 0; mm < 4; mm++) {
                const int ar = warp_m * 64 + mm * 16 + g;
                af[mm][0] = __float_as_uint(Ah[ar * ASTR + kb + tg]);
                af[mm][1] = __float_as_uint(Ah[(ar + 8) * ASTR + kb + tg]);
                af[mm][2] = __float_as_uint(Ah[ar * ASTR + kb + tg + 4]);
                af[mm][3] = __float_as_uint(Ah[(ar + 8) * ASTR + kb + tg + 4]);
            }
            #pragma unroll
            for (int nn = 0; nn < 4; nn++) {
                const int bc = warp_n * 32 + nn * 8 + g;
                bf[nn][0] = __float_as_uint(Bl[(kb + tg) * BSTR + bc]);
                bf[nn][1] = __float_as_uint(Bl[(kb + tg + 4) * BSTR + bc]);
            }
            #pragma unroll
            for (int mm = 0; mm < 4; mm++)
                #pragma unroll
                for (int nn = 0; nn < 4; nn++)
                    MMA_TF32(acc[mm][nn], af[mm][0], af[mm][1], af[mm][2], af[mm][3],
                             bf[nn][0], bf[nn][1]);
            #pragma unroll
            for (int nn = 0; nn < 4; nn++) {
                const int bc = warp_n * 32 + nn * 8 + g;
                bf[nn][0] = __float_as_uint(Bh[(kb + tg) * BSTR + bc]);
                bf[nn][1] = __float_as_uint(Bh[(kb + tg + 4) * BSTR + bc]);
            }
            #pragma unroll
            for (int mm = 0; mm < 4; mm++)
                #pragma unroll
                for (int nn = 0; nn < 4; nn++)
                    MMA_TF32(acc[mm][nn], af[mm][0], af[mm][1], af[mm][2], af[mm][3],
                             bf[nn][0], bf[nn][1]);
            #pragma unroll
            for (int mm = 0; mm < 4; mm++) {
                const int ar = warp_m * 64 + mm * 16 + g;
                af[mm][0] = __float_as_uint(Al[ar * ASTR + kb + tg]);
                af[mm][1] = __float_as_uint(Al[(ar + 8) * ASTR + kb + tg]);
                af[mm][2] = __float_as_uint(Al[ar * ASTR + kb + tg + 4]);
                af[mm][3] = __float_as_uint(Al[(ar + 8) * ASTR + kb + tg + 4]);
            }
            #pragma unroll
            for (int mm = 0; mm < 4; mm++)
                #pragma unroll
                for (int nn = 0; nn < 4; nn++)
                    MMA_TF32(acc[mm][nn], af[mm][0], af[mm][1], af[mm][2], af[mm][3],
                             bf[nn][0], bf[nn][1]);
        }
        __syncthreads();
    }

    // ---- normal store: dist[row][col] = sq[col] - 2*acc ----
    #pragma unroll
    for (int nn = 0; nn < 4; nn++) {
        const int col = col0 + warp_n * 32 + nn * 8 + tg * 2;
        const float bv0 = sq[col], bv1 = sq[col + 1];
        #pragma unroll
        for (int mm = 0; mm < 4; mm++) {
            const int row = row0 + warp_m * 64 + mm * 16 + g;
            float2 o0, o1;
            o0.x = bv0 - 2.f * acc[mm][nn][0];
            o0.y = bv1 - 2.f * acc[mm][nn][1];
            o1.x = bv0 - 2.f * acc[mm][nn][2];
            o1.y = bv1 - 2.f * acc[mm][nn][3];
            *(float2*)(C + (size_t)row * NN + col)       = o0;
            *(float2*)(C + (size_t)(row + 8) * NN + col) = o1;
        }
    }

    // ---- mirrored store: dist[col][row] = sq[row] - 2*acc (off-diagonal) ----
    if (bi != bj) {
        // stage transposed tile in smem (Sc[local_col * 132 + local_row])
        float* Sc = sm;     // mainloop buffers are dead past the final sync
        #pragma unroll
        for (int mm = 0; mm < 4; mm++) {
            const int lr = warp_m * 64 + mm * 16 + g;
            const float s0 = sq[row0 + lr], s1 = sq[row0 + lr + 8];
            #pragma unroll
            for (int nn = 0; nn < 4; nn++) {
                const int lc = warp_n * 32 + nn * 8 + tg * 2;
                Sc[lc * 132 + lr]            = s0 - 2.f * acc[mm][nn][0];
                Sc[(lc + 1) * 132 + lr]      = s0 - 2.f * acc[mm][nn][1];
                Sc[lc * 132 + lr + 8]        = s1 - 2.f * acc[mm][nn][2];
                Sc[(lc + 1) * 132 + lr + 8]  = s1 - 2.f * acc[mm][nn][3];
            }
        }
        __syncthreads();
        // coalesced write-out: warp w handles mirror rows w, w+8, ...
        #pragma unroll
        for (int it = 0; it < 16; it++) {
            const int lc = warp + it * 8;
            const float4 v = *(const float4*)&Sc[lc * 132 + lane * 4];
            *(float4*)(C + (size_t)(col0 + lc) * NN + row0 + lane * 4) = v;
        }
    }
}

// ---------------- fallback SIMT GEMM (used only when N % 128 != 0) ----------
#define GBM 128
#define GBN 64
#define GBK 32

__global__ __launch_bounds__(256, 2) void gemm_k(
    const float* __restrict__ A, const float* __restrict__ B,
    const float* __restrict__ bias, float* __restrict__ C,
    int M, int K, int N, int mode)
{
    __shared__ float As[GBK][GBM + 4];
    __shared__ float Bs[GBK][GBN];
    const int tid  = threadIdx.x;
    const int row0 = blockIdx.y * GBM;
    const int col0 = blockIdx.x * GBN;
    const int tr = tid >> 4;
    const int tc = tid & 15;

    float acc[8][4];
    #pragma unroll
    for (int i = 0; i < 8; i++)
        #pragma unroll
        for (int j = 0; j < 4; j++) acc[i][j] = 0.f;

    const int ktiles = K / GBK;
    for (int kt = 0; kt < ktiles; kt++) {
        #pragma unroll
        for (int p = 0; p < 4; p++) {
            int lin = tid + 256 * p;
            int r = lin >> 3, q = lin & 7;
            const float4 v = *(const float4*)(A + (size_t)(row0 + r) * K + kt * GBK + q * 4);
            As[q * 4 + 0][r] = v.x; As[q * 4 + 1][r] = v.y;
            As[q * 4 + 2][r] = v.z; As[q * 4 + 3][r] = v.w;
        }
        #pragma unroll
        for (int p = 0; p < 2; p++) {
            int lin = tid + 256 * p;
            int kr = lin >> 4, j4 = lin & 15;
            *(float4*)&Bs[kr][j4 * 4] =
                *(const float4*)(B + (size_t)(kt * GBK + kr) * N + col0 + j4 * 4);
        }
        __syncthreads();
        #pragma unroll
        for (int k = 0; k < GBK; k++) {
            float a[8], b[4];
            *(float4*)&a[0] = *(const float4*)&As[k][tr * 8];
            *(float4*)&a[4] = *(const float4*)&As[k][tr * 8 + 4];
            *(float4*)&b[0] = *(const float4*)&Bs[k][tc * 4];
            #pragma unroll
            for (int i = 0; i < 8; i++)
                #pragma unroll
                for (int j = 0; j < 4; j++)
                    acc[i][j] = fmaf(a[i], b[j], acc[i][j]);
        }
        __syncthreads();
    }

    float bv[4];
    #pragma unroll
    for (int j = 0; j < 4; j++) bv[j] = bias[col0 + tc * 4 + j];

    #pragma unroll
    for (int i = 0; i < 8; i++) {
        const int row = row0 + tr * 8 + i;
        float4 o;
        o.x = fmaxf(acc[i][0] + bv[0], 0.f);
        o.y = fmaxf(acc[i][1] + bv[1], 0.f);
        o.z = fmaxf(acc[i][2] + bv[2], 0.f);
        o.w = fmaxf(acc[i][3] + bv[3], 0.f);
        *(float4*)(C + (size_t)row * N + col0 + tc * 4) = o;
    }
}

// ---------------- fusion kernels (factored first MLP layer) ------------------
__global__ __launch_bounds__(256) void static_fuse_k(
    const float* __restrict__ eW, const float* __restrict__ P,
    const void* __restrict__ ei, float* __restrict__ hid)
{
    const int e  = blockIdx.x * 4 + (threadIdx.x >> 6);
    const int c4 = threadIdx.x & 63;
    const long long s = load_ei(ei, e);
    const long long d = load_ei(ei, (long long)NE + e);
    const float4 a = *(const float4*)(eW + (size_t)e * HH + c4 * 4);
    const float4 ps = *(const float4*)(P + (size_t)s * HH + c4 * 4);
    const float4 pd = *(const float4*)(P + (size_t)d * HH + c4 * 4);
    float4 o;
    o.x = fmaxf(a.x + ps.x - pd.x, 0.f);
    o.y = fmaxf(a.y + ps.y - pd.y, 0.f);
    o.z = fmaxf(a.z + ps.z - pd.z, 0.f);
    o.w = fmaxf(a.w + ps.w - pd.w, 0.f);
    *(float4*)(hid + (size_t)e * HH + c4 * 4) = o;
}

__global__ __launch_bounds__(256) void dyn_fuse_k(
    const float* __restrict__ P1, const float* __restrict__ P2,
    const int* __restrict__ knn, const float* __restrict__ bias,
    float* __restrict__ hid)
{
    const int e  = blockIdx.x * 4 + (threadIdx.x >> 6);
    const int c4 = threadIdx.x & 63;
    const int i = e >> 4;
    const int j = knn[e];
    const float4 p1 = *(const float4*)(P1 + (size_t)i * HH + c4 * 4);
    const float4 pi = *(const float4*)(P2 + (size_t)i * HH + c4 * 4);
    const float4 pj = *(const float4*)(P2 + (size_t)j * HH + c4 * 4);
    const float4 b  = *(const float4*)(bias + c4 * 4);
    float4 o;
    o.x = fmaxf(p1.x - pi.x + pj.x + b.x, 0.f);
    o.y = fmaxf(p1.y - pi.y + pj.y + b.y, 0.f);
    o.z = fmaxf(p1.z - pi.z + pj.z + b.z, 0.f);
    o.w = fmaxf(p1.w - pi.w + pj.w + b.w, 0.f);
    *(float4*)(hid + (size_t)e * HH + c4 * 4) = o;
}

// ---------------- small helper kernels --------------------------------------
__global__ void rownorm_k(const float* __restrict__ x, float* __restrict__ sq)
{
    const int row  = blockIdx.x * 8 + (threadIdx.x >> 5);
    const int lane = threadIdx.x & 31;
    const float* p = x + (size_t)row * DD;
    float s = 0.f;
    #pragma unroll
    for (int q = 0; q < 4; q++) { float v = p[lane + 32 * q]; s = fmaf(v, v, s); }
    #pragma unroll
    for (int o = 16; o > 0; o >>= 1) s += __shfl_xor_sync(0xffffffffu, s, o);
    if (lane == 0) sq[row] = s;
}

__global__ void transpose_k(const float* __restrict__ in, float* __restrict__ out)
{
    __shared__ float t[32][33];
    const int j0 = blockIdx.x * 32, k0 = blockIdx.y * 32;
    for (int r = threadIdx.y; r < 32; r += 8)
        t[r][threadIdx.x] = in[(size_t)(j0 + r) * DD + k0 + threadIdx.x];
    __syncthreads();
    for (int r = threadIdx.y; r < 32; r += 8)
        out[(size_t)(k0 + r) * NN + j0 + threadIdx.x] = t[threadIdx.x][r];
}

__global__ __launch_bounds__(256) void topk_k(const float* __restrict__ dist,
                                              int* __restrict__ knn)
{
    __shared__ float sd[256 * 16];
    __shared__ int   si[256 * 16];
    const int i = blockIdx.x, t = threadIdx.x;
    const float* row = dist + (size_t)i * NN;

    float ld[KK]; int li[KK];
    #pragma unroll
    for (int q = 0; q < KK; q++) { ld[q] = __int_as_float(0x7f800000); li[q] = 0x7FFFFFFF; }
    float worst = __int_as_float(0x7f800000); int worsti = 0x7FFFFFFF;

    for (int j = t; j < NN; j += 256) {
        const float r = row[j];
        if (r < worst || (r == worst && j < worsti)) {
            int p = KK - 1;
            while (p > 0) {
                const bool gt = (ld[p-1] > r) || (ld[p-1] == r && li[p-1] > j);
                if (!gt) break;
                ld[p] = ld[p-1]; li[p] = li[p-1]; p--;
            }
            ld[p] = r; li[p] = j;
            worst = ld[KK-1]; worsti = li[KK-1];
        }
    }
    #pragma unroll
    for (int q = 0; q < KK; q++) { sd[t * KK + q] = ld[q]; si[t * KK + q] = li[q]; }

    for (int s = 128; s > 0; s >>= 1) {
        __syncthreads();
        if (t < s) {
            float od[KK]; int oi[KK];
            int pa = t * KK, pb = (t + s) * KK;
            const int ea_ = pa + KK, eb_ = pb + KK;
            #pragma unroll
            for (int q = 0; q < KK; q++) {
                const float da = (pa < ea_) ? sd[pa] : __int_as_float(0x7f800000);
                const int   ia = (pa < ea_) ? si[pa] : 0x7FFFFFFF;
                const float db = (pb < eb_) ? sd[pb] : __int_as_float(0x7f800000);
                const int   ib = (pb < eb_) ? si[pb] : 0x7FFFFFFF;
                const bool ta = (da < db) || (da == db && ia < ib);
                if (ta) { od[q] = da; oi[q] = ia; pa++; }
                else    { od[q] = db; oi[q] = ib; pb++; }
            }
            #pragma unroll
            for (int q = 0; q < KK; q++) { sd[t * KK + q] = od[q]; si[t * KK + q] = oi[q]; }
        }
    }
    __syncthreads();
    if (t < KK) knn[i * KK + t] = si[t];
}

__global__ void concat_k(const float* __restrict__ a, const float* __restrict__ b,
                         float* __restrict__ out)
{
    const int i = blockIdx.x, c = threadIdx.x;
    out[(size_t)i * 256 + c] = (c < DD) ? a[i * DD + c] : b[i * DD + c - DD];
}

// ---------------- host orchestration ---------------------------------------
static inline void gemm(const float* A, const float* B, const float* bias, float* C,
                        int M, int K, int N, int mode, const void* ei = nullptr)
{
    if ((N % TBN) == 0 && (M % TBM) == 0) {
        dim3 g(N / TBN, M / TBM);
        mma3_gemm_k<<<g, 256, MMA3_SMEM_BYTES>>>(A, B, bias, C, M, K, N, mode, ei);
    } else {
        dim3 g(N / GBN, M / GBM);
        gemm_k<<<g, 256>>>(A, B, bias, C, M, K, N, mode);
    }
}

extern "C" void kernel_launch(void* const* d_in, const int* in_sizes, int n_in,
                              void* d_out, int out_size)
{
    const float* x    = (const float*)d_in[0];
    const float* ea_i = (const float*)d_in[1];
    const float* sW1  = (const float*)d_in[2];
    const float* sb1  = (const float*)d_in[3];
    const float* sW2  = (const float*)d_in[4];
    const float* sb2  = (const float*)d_in[5];
    const float* uW1  = (const float*)d_in[6];
    const float* ub1  = (const float*)d_in[7];
    const float* uW2  = (const float*)d_in[8];
    const float* ub2  = (const float*)d_in[9];
    const float* rW   = (const float*)d_in[10];
    const float* rb   = (const float*)d_in[11];
    const float* dW1  = (const float*)d_in[12];
    const float* db1  = (const float*)d_in[13];
    const float* dW2  = (const float*)d_in[14];
    const float* db2  = (const float*)d_in[15];
    const float* dUW1 = (const float*)d_in[16];
    const float* dUb1 = (const float*)d_in[17];
    const float* dUW2 = (const float*)d_in[18];
    const float* dUb2 = (const float*)d_in[19];
    const float* fW1  = (const float*)d_in[20];
    const float* fb1  = (const float*)d_in[21];
    const float* fW2  = (const float*)d_in[22];
    const float* fb2  = (const float*)d_in[23];
    const void*  ei   = d_in[24];

    cudaFuncSetAttribute(mma3_gemm_k, cudaFuncAttributeMaxDynamicSharedMemorySize,
                         MMA3_SMEM_BYTES);
    cudaFuncSetAttribute(dist_sym_k, cudaFuncAttributeMaxDynamicSharedMemorySize,
                         MMA3_SMEM_BYTES);

    float *msg, *hid, *ea0, *ea1, *xs0, *xs1, *xd0, *xd1;
    float *agg, *tmpN, *P2, *cat, *sq, *xT, *dist, *zero;
    int   *knn;
    cudaGetSymbolAddress((void**)&msg,  g_msg);
    cudaGetSymbolAddress((void**)&hid,  g_hid);
    cudaGetSymbolAddress((void**)&ea0,  g_ea0);
    cudaGetSymbolAddress((void**)&ea1,  g_ea1);
    cudaGetSymbolAddress((void**)&xs0,  g_xs0);
    cudaGetSymbolAddress((void**)&xs1,  g_xs1);
    cudaGetSymbolAddress((void**)&xd0,  g_xd0);
    cudaGetSymbolAddress((void**)&xd1,  g_xd1);
    cudaGetSymbolAddress((void**)&agg,  g_agg);
    cudaGetSymbolAddress((void**)&tmpN, g_tmpN);
    cudaGetSymbolAddress((void**)&P2,   g_P2);
    cudaGetSymbolAddress((void**)&cat,  g_cat);
    cudaGetSymbolAddress((void**)&sq,   g_sq);
    cudaGetSymbolAddress((void**)&xT,   g_xT);
    cudaGetSymbolAddress((void**)&dist, g_dist);
    cudaGetSymbolAddress((void**)&zero, g_zero);
    cudaGetSymbolAddress((void**)&knn,  g_knn);

    detect_ei_k<<<1, 1>>>(ei);

    // ---------------- static branch: 3 conv layers + 2 edge refiners --------
    const float* xs_in = x;
    const float* ea_in = ea_i;
    float* xs_bufs[2] = { xs0, xs1 };
    float* ea_bufs[2] = { ea0, ea1 };
    for (int i = 0; i < 3; i++) {
        const float* W1 = sW1 + (size_t)i * 192 * HH;
        gemm(ea_in, W1, sb1 + i * HH, hid, NE, DE, HH, 2);              // eW + b1
        gemm(xs_in, W1 + (size_t)DE * HH, zero, tmpN, NN, DD, HH, 2);   // P = xs@W_x
        static_fuse_k<<<NE / 4, 256>>>(hid, tmpN, ei, msg);
        cudaMemsetAsync(agg, 0, (size_t)NN * DD * sizeof(float));
        gemm(msg, sW2 + (size_t)i * HH * DD, sb2 + i * DD, agg, NE, HH, DD, 3, ei);
        gemm(agg,  uW1 + (size_t)i * DD * HH, ub1 + i * HH, tmpN, NN, DD, HH, 0);
        float* xs_out = xs_bufs[i & 1];
        gemm(tmpN, uW2 + (size_t)i * HH * DD, ub2 + i * DD, xs_out, NN, HH, DD, 0);
        if (i < 2) {
            float* ea_out = ea_bufs[i & 1];
            gemm(ea_in, rW + (size_t)i * DE * DE, rb + i * DE, ea_out, NE, DE, DE, 0);
            ea_in = ea_out;
        }
        xs_in = xs_out;
    }

    // ---------------- dynamic branch: 2 kNN conv layers ---------------------
    const float* xd_in = x;
    float* xd_bufs[2] = { xd0, xd1 };
    for (int i = 0; i < 2; i++) {
        rownorm_k<<<NN / 8, 256>>>(xd_in, sq);
        transpose_k<<<dim3(NN / 32, DD / 32), dim3(32, 8)>>>(xd_in, xT);
        dist_sym_k<<<dim3(NN / TBM, NN / TBM), 256, MMA3_SMEM_BYTES>>>(xd_in, xT, sq, dist);
        topk_k<<<NN, 256>>>(dist, knn);
        const float* W1 = dW1 + (size_t)i * 2 * DD * HH;
        gemm(xd_in, W1, zero, tmpN, NN, DD, HH, 2);                     // P1 = xd@W_top
        gemm(xd_in, W1 + (size_t)DD * HH, zero, P2, NN, DD, HH, 2);     // P2 = xd@W_bot
        dyn_fuse_k<<<NE / 4, 256>>>(tmpN, P2, knn, db1 + i * HH, msg);
        cudaMemsetAsync(agg, 0, (size_t)NN * DD * sizeof(float));
        gemm(msg, dW2 + (size_t)i * HH * DD, db2 + i * DD, agg, NE, HH, DD, 4);
        gemm(agg,  dUW1 + (size_t)i * DD * HH, dUb1 + i * HH, tmpN, NN, DD, HH, 0);
        float* xd_out = xd_bufs[i];
        gemm(tmpN, dUW2 + (size_t)i * HH * DD, dUb2 + i * DD, xd_out, NN, HH, DD, 0);
        xd_in = xd_out;
    }

    // ---------------- fuse ---------------------------------------------------
    concat_k<<<NN, 256>>>(xs_in, xd_in, cat);
    gemm(cat,  fW1, fb1, tmpN, NN, 2 * DD, HH, 0);
    gemm(tmpN, fW2, fb2, (float*)d_out, NN, HH, DD, 0);
}